// round 8
// baseline (speedup 1.0000x reference)
#include <cuda_runtime.h>
#include <cstdint>
#include <cstddef>

#define TSTEPS 512
#define BATCH  64
#define DIM    512
#define HID    512
#define GDIM   2048            // 4*HID
#define GRID_BLOCKS 64
#define JB 8                   // hidden columns per recurrent block
#define HS_STRIDE 516          // padded (512+4) to kill bank conflicts
#define RED_B 36               // padded partial row stride
#define RED_W (64 * RED_B)     // one warp's partial tile

// ---------------- scratch (static device allocations; no cudaMalloc) -------
__device__ float g_xproj[(size_t)TSTEPS * BATCH * GDIM];  // 256 MB: x@W_ih^T + bias
__device__ float g_hbuf[2][BATCH * HID];                  // ping-pong hidden state
// per-producer-BLOCK monotonic counters, padded to 32B sectors.
// counter for block blk lives at g_cnt2[blk*8]; value = 8 * (1 + steps done).
__device__ unsigned g_cnt2[GRID_BLOCKS * 8];

// ---------------- helpers ---------------------------------------------------
__device__ __forceinline__ float tf32r(float x) {
    uint32_t r; asm("cvt.rna.tf32.f32 %0, %1;" : "=r"(r) : "f"(x));
    return __uint_as_float(r);
}
__device__ __forceinline__ void mma_tf32(float c[4], const uint32_t a[4], const uint32_t b[2]) {
    asm volatile(
        "mma.sync.aligned.m16n8k8.row.col.f32.tf32.tf32.f32 "
        "{%0,%1,%2,%3}, {%4,%5,%6,%7}, {%8,%9}, {%0,%1,%2,%3};"
        : "+f"(c[0]), "+f"(c[1]), "+f"(c[2]), "+f"(c[3])
        : "r"(a[0]), "r"(a[1]), "r"(a[2]), "r"(a[3]), "r"(b[0]), "r"(b[1]));
}
__device__ __forceinline__ float ex2f(float x) { float y; asm("ex2.approx.f32 %0, %1;" : "=f"(y) : "f"(x)); return y; }
__device__ __forceinline__ float rcpf(float x) { float y; asm("rcp.approx.f32 %0, %1;" : "=f"(y) : "f"(x)); return y; }
__device__ __forceinline__ float sigf(float x)  { return rcpf(1.0f + ex2f(-1.4426950408889634f * x)); }
__device__ __forceinline__ float tanhf_(float x){ return 2.0f * sigf(2.0f * x) - 1.0f; }

__device__ __forceinline__ unsigned ld_acq(const unsigned* p) {
    unsigned v; asm volatile("ld.acquire.gpu.global.u32 %0, [%1];" : "=r"(v) : "l"(p)); return v;
}
__device__ __forceinline__ void arrive_release(unsigned* p) {
    asm volatile("red.release.gpu.global.add.u32 [%0], 1;" :: "l"(p) : "memory");
}
__device__ __forceinline__ void cp16(uint32_t s, const void* g) {
    asm volatile("cp.async.cg.shared.global [%0], [%1], 16;" :: "r"(s), "l"(g));
}

// ============================================================================
// Kernel 1: x_proj[m, g] = sum_d X[m,d]*W_ih[g,d] + (b_ih[g]+b_hh[g])
// M = T*B = 32768, K = 512, N = 2048.  TF32 mma.sync, 128x128x32 tiles.
// Also resets the per-block counters for the lstm kernel that follows.
// ============================================================================
__global__ void __launch_bounds__(256) xproj_kernel(
    const float* __restrict__ X, const float* __restrict__ Wih,
    const float* __restrict__ b_ih, const float* __restrict__ b_hh)
{
    {
        int bid = blockIdx.y * gridDim.x + blockIdx.x;      // 0..4095
        if (threadIdx.x == 0 && bid < GRID_BLOCKS * 8) g_cnt2[bid] = 0u;
    }

    __shared__ float As[128][36];
    __shared__ float Bs[32][132];

    const int m0 = blockIdx.y * 128;
    const int n0 = blockIdx.x * 128;
    const int tid  = threadIdx.x;
    const int lane = tid & 31;
    const int warp = tid >> 5;
    const int wm = warp >> 1;       // 0..3 : 32 output rows each
    const int wn = warp & 1;        // 0..1 : 64 output cols each
    const int gid = lane >> 2;      // 0..7
    const int tig = lane & 3;       // 0..3

    float acc[2][8][4];
    #pragma unroll
    for (int mt = 0; mt < 2; mt++)
        #pragma unroll
        for (int nt = 0; nt < 8; nt++)
            #pragma unroll
            for (int q = 0; q < 4; q++) acc[mt][nt][q] = 0.0f;

    const int lr = tid >> 3;          // 0..31
    const int lc = (tid & 7) * 4;     // 0..28

    for (int k0 = 0; k0 < DIM; k0 += 32) {
        __syncthreads();
        #pragma unroll
        for (int p = 0; p < 4; p++) {
            int r = lr + p * 32;
            float4 v = *(const float4*)(X + (size_t)(m0 + r) * DIM + k0 + lc);
            As[r][lc+0] = tf32r(v.x); As[r][lc+1] = tf32r(v.y);
            As[r][lc+2] = tf32r(v.z); As[r][lc+3] = tf32r(v.w);
        }
        #pragma unroll
        for (int p = 0; p < 4; p++) {
            int n = lr + p * 32;
            float4 v = *(const float4*)(Wih + (size_t)(n0 + n) * DIM + k0 + lc);
            Bs[lc+0][n] = tf32r(v.x); Bs[lc+1][n] = tf32r(v.y);
            Bs[lc+2][n] = tf32r(v.z); Bs[lc+3][n] = tf32r(v.w);
        }
        __syncthreads();

        #pragma unroll
        for (int ks = 0; ks < 4; ks++) {
            const int kb = ks * 8;
            uint32_t a[2][4], b[8][2];
            #pragma unroll
            for (int mt = 0; mt < 2; mt++) {
                int row = wm * 32 + mt * 16;
                a[mt][0] = __float_as_uint(As[row + gid    ][kb + tig    ]);
                a[mt][1] = __float_as_uint(As[row + gid + 8][kb + tig    ]);
                a[mt][2] = __float_as_uint(As[row + gid    ][kb + tig + 4]);
                a[mt][3] = __float_as_uint(As[row + gid + 8][kb + tig + 4]);
            }
            #pragma unroll
            for (int nt = 0; nt < 8; nt++) {
                int col = wn * 64 + nt * 8 + gid;
                b[nt][0] = __float_as_uint(Bs[kb + tig    ][col]);
                b[nt][1] = __float_as_uint(Bs[kb + tig + 4][col]);
            }
            #pragma unroll
            for (int mt = 0; mt < 2; mt++)
                #pragma unroll
                for (int nt = 0; nt < 8; nt++)
                    mma_tf32(acc[mt][nt], a[mt], b[nt]);
        }
    }

    // epilogue: add bias, write fp32
    #pragma unroll
    for (int mt = 0; mt < 2; mt++) {
        #pragma unroll
        for (int nt = 0; nt < 8; nt++) {
            int row = m0 + wm * 32 + mt * 16 + gid;
            int col = n0 + wn * 64 + nt * 8 + 2 * tig;
            float bz0 = b_ih[col]     + b_hh[col];
            float bz1 = b_ih[col + 1] + b_hh[col + 1];
            float2 v0 = make_float2(acc[mt][nt][0] + bz0, acc[mt][nt][1] + bz1);
            float2 v1 = make_float2(acc[mt][nt][2] + bz0, acc[mt][nt][3] + bz1);
            *(float2*)(g_xproj + (size_t)row       * GDIM + col) = v0;
            *(float2*)(g_xproj + (size_t)(row + 8) * GDIM + col) = v1;
        }
    }
}

// ============================================================================
// Kernel 2: persistent recurrence with PER-CHUNK dataflow pipelining into
// warp-private h_s column slices (fixes the R7 aliasing bug).
// Warp w's K-slice [64w, 64w+64) = 8 chunks of 8 cols; chunk kk is produced
// entirely by block 8w+kk (counter g_cnt2[(8w+kk)*8], +8 per step). Issue
// phase polls the 8 counters lane-parallel, cp.asyncs each ready chunk into
// h_s[:, kbase+8kk] (own commit_group, in order). Compute uses incremental
// wait_group(7-kk) so chunk k+1's L2 latency hides behind chunk k's MMAs.
// Union of all warps' polls = all 64 producers, and arrivals are post-bar-A,
// so the h ping-pong reuse is ordered (same argument as R4).
// ============================================================================
__global__ void __launch_bounds__(256, 1) lstm_kernel(
    const float* __restrict__ mask, const float* __restrict__ h0,
    const float* __restrict__ Whh, float* __restrict__ out)
{
    extern __shared__ float smem[];
    float* h_s  = smem;                      // 64 x 516  (also W staging at init)
    float* red  = h_s  + 64 * HS_STRIDE;     // 8 x 64 x 36 partials
    float* h0_s = red  + 8 * RED_W;          // 512
    float* c_s  = h0_s + 512;                // 512

    const int tid  = threadIdx.x;
    const int blk  = blockIdx.x;
    const int j0   = blk * JB;
    const int lane = tid & 31;
    const int warp = tid >> 5;               // 0..7 -> K-slice
    const int gid  = lane >> 2;              // 0..7
    const int tig  = lane & 3;               // 0..3
    const int kbase = warp * 64;

    // --- stage W_hh slice (32 rows x 512) into h_s temporarily, as tf32
    for (int i = tid; i < 32 * 128; i += 256) {
        int r  = i >> 7;                 // 0..31  (gate*8 + jl)
        int k4 = (i & 127) * 4;
        int gate = r >> 3, jl = r & 7;
        float4 v = *(const float4*)(Whh + (size_t)(gate * HID + j0 + jl) * HID + k4);
        float* d = &h_s[r * HS_STRIDE + k4];
        d[0] = tf32r(v.x); d[1] = tf32r(v.y); d[2] = tf32r(v.z); d[3] = tf32r(v.w);
    }
    // --- h0 slice, c0 = h0; publish tf32-rounded h0 to ping buffer 0
    for (int i = tid; i < 512; i += 256) {
        int b = i >> 3, jl = i & 7;
        float v = h0[b * HID + j0 + jl];
        h0_s[i] = v;
        c_s[i]  = v;
        g_hbuf[0][b * HID + j0 + jl] = tf32r(v);
    }
    __syncthreads();

    // --- preload this warp's B fragments: b[kk][nt][2], resident forever
    uint32_t breg[8][4][2];
    #pragma unroll
    for (int kk = 0; kk < 8; kk++)
        #pragma unroll
        for (int nt = 0; nt < 4; nt++) {
            const float* pb = &h_s[(nt * 8 + gid) * HS_STRIDE + kbase + kk * 8 + tig];
            breg[kk][nt][0] = __float_as_uint(pb[0]);
            breg[kk][nt][1] = __float_as_uint(pb[4]);
        }
    __syncthreads();
    // h0 published (+1 per warp; counter reaches 8 = 8*(0+1))
    if (lane == 0) arrive_release(&g_cnt2[blk * 8]);

    const int rb  = tid >> 2;          // 0..63 batch row for reduce phase
    const int jl0 = (tid & 3) * 2;     // 0,2,4,6

    const uint32_t hss = (uint32_t)__cvta_generic_to_shared(h_s);
    // poll address for this warp+lane: counter of block 8*warp + (lane&7)
    const unsigned* pollp = &g_cnt2[(warp * 8 + (lane & 7)) * 8];

    // prefetch x_proj + mask for t=0
    const float* xp0 = g_xproj + (size_t)rb * GDIM + j0 + jl0;
    float2 xq[4];
    #pragma unroll
    for (int g = 0; g < 4; g++) xq[g] = *(const float2*)(xp0 + g * HID);
    float mval = mask[rb];

    for (int t = 0; t < TSTEPS; t++) {
        const float* hin  = g_hbuf[t & 1];
        float*       hout = g_hbuf[(t + 1) & 1];

        // ==== ISSUE PHASE: per-chunk poll + cp.async (in order) ====
        {
            const unsigned want = 8u * (unsigned)(t + 1);
            int kk = 0;
            while (kk < 8) {
                unsigned cv  = ld_acq(pollp);
                unsigned rdy = __ballot_sync(0xffffffffu, cv >= want);
                while (kk < 8 && ((rdy >> kk) & 1u)) {
                    // chunk kk: 64 rows x 8 cols (32B/row = 2 cp16)
                    const int coff = kbase + kk * 8;
                    #pragma unroll
                    for (int i2 = 0; i2 < 4; i2++) {
                        int e    = i2 * 32 + lane;   // 0..127
                        int row  = e >> 1;
                        int half = (e & 1) * 4;
                        cp16(hss + (uint32_t)(row * HS_STRIDE + coff + half) * 4,
                             hin + (size_t)row * HID + coff + half);
                    }
                    asm volatile("cp.async.commit_group;" ::: "memory");
                    kk++;
                }
            }
        }

        // ==== COMPUTE PHASE: incremental wait + 16 mma per chunk ====
        float acc[4][4][4];
        #pragma unroll
        for (int mt = 0; mt < 4; mt++)
            #pragma unroll
            for (int nt = 0; nt < 4; nt++)
                #pragma unroll
                for (int q = 0; q < 4; q++) acc[mt][nt][q] = 0.0f;

#define DO_CHUNK(KK, PEND)                                                      \
        {                                                                       \
            asm volatile("cp.async.wait_group " #PEND ";" ::: "memory");        \
            __syncwarp();                                                       \
            uint32_t a[4][4];                                                   \
            _Pragma("unroll")                                                   \
            for (int mt = 0; mt < 4; mt++) {                                    \
                const float* pa = &h_s[(mt * 16 + gid) * HS_STRIDE              \
                                       + kbase + (KK) * 8 + tig];               \
                a[mt][0] = __float_as_uint(pa[0]);                              \
                a[mt][1] = __float_as_uint(pa[8 * HS_STRIDE]);                  \
                a[mt][2] = __float_as_uint(pa[4]);                              \
                a[mt][3] = __float_as_uint(pa[8 * HS_STRIDE + 4]);              \
            }                                                                   \
            _Pragma("unroll")                                                   \
            for (int mt = 0; mt < 4; mt++)                                      \
                _Pragma("unroll")                                               \
                for (int nt = 0; nt < 4; nt++)                                  \
                    mma_tf32(acc[mt][nt], a[mt], breg[KK][nt]);                 \
        }
        DO_CHUNK(0, 7) DO_CHUNK(1, 6) DO_CHUNK(2, 5) DO_CHUNK(3, 4)
        DO_CHUNK(4, 3) DO_CHUNK(5, 2) DO_CHUNK(6, 1) DO_CHUNK(7, 0)
#undef DO_CHUNK

        // ---- store partials: red[warp][row][col]
        float* rw = red + warp * RED_W;
        #pragma unroll
        for (int mt = 0; mt < 4; mt++)
            #pragma unroll
            for (int nt = 0; nt < 4; nt++) {
                int row = mt * 16 + gid;
                int col = nt * 8 + 2 * tig;
                float* rp = &rw[row * RED_B + col];
                *(float2*)rp                 = make_float2(acc[mt][nt][0], acc[mt][nt][1]);
                *(float2*)(rp + 8 * RED_B)   = make_float2(acc[mt][nt][2], acc[mt][nt][3]);
            }
        __syncthreads();                       // bar A: partials complete

        // ---- reduce 8 partials + x_proj, LSTM cell, mask blend, publish h
        float s[4][2];
        #pragma unroll
        for (int g = 0; g < 4; g++) { s[g][0] = xq[g].x; s[g][1] = xq[g].y; }
        #pragma unroll
        for (int w = 0; w < 8; w++) {
            const float* rr = red + w * RED_W + rb * RED_B + jl0;
            #pragma unroll
            for (int g = 0; g < 4; g++) {
                float2 v = *(const float2*)(rr + g * 8);
                s[g][0] += v.x; s[g][1] += v.y;
            }
        }
        float hv[2], cv[2];
        #pragma unroll
        for (int u = 0; u < 2; u++) {
            float iv = sigf(s[0][u]);
            float fv = sigf(s[1][u]);
            float gv = tanhf_(s[2][u]);
            float ov = sigf(s[3][u]);
            int p = rb * 8 + jl0 + u;
            float c = fv * c_s[p] + iv * gv;
            float h = ov * tanhf_(c);
            float z = h0_s[p];                   // h0 == c0
            h = h * mval + z * (1.0f - mval);
            c = c * mval + z * (1.0f - mval);
            c_s[p] = c;
            hv[u] = h; cv[u] = c;
            hout[rb * HID + j0 + jl0 + u] = tf32r(h);
        }
        // this warp's hout rows stored -> release-arrive (+1 of 8 per block)
        __syncwarp();
        if (lane == 0) arrive_release(&g_cnt2[blk * 8]);

        // ---- shadow: out[] stores + next-step prefetch (off critical path)
        #pragma unroll
        for (int u = 0; u < 2; u++) {
            int gcol = j0 + jl0 + u;
            out[(size_t)t * BATCH * HID + rb * HID + gcol] = hv[u];
            if (t == TSTEPS - 1) {
                out[(size_t)TSTEPS * BATCH * HID               + rb * HID + gcol] = hv[u];
                out[(size_t)TSTEPS * BATCH * HID + BATCH * HID + rb * HID + gcol] = cv[u];
            }
        }
        if (t + 1 < TSTEPS) {
            const float* xp = g_xproj + (size_t)(t + 1) * BATCH * GDIM
                            + (size_t)rb * GDIM + j0 + jl0;
            #pragma unroll
            for (int g = 0; g < 4; g++) xq[g] = *(const float2*)(xp + g * HID);
            mval = mask[(t + 1) * BATCH + rb];
        }
        __syncthreads();                       // bar B: red safe to overwrite
    }
}

// ============================================================================
extern "C" void kernel_launch(void* const* d_in, const int* in_sizes, int n_in,
                              void* d_out, int out_size) {
    const float* inputs = (const float*)d_in[0];   // [512,64,512]
    const float* mask   = (const float*)d_in[1];   // [512,64]
    const float* h0     = (const float*)d_in[2];   // [64,512]
    const float* W_ih   = (const float*)d_in[3];   // [2048,512]
    const float* W_hh   = (const float*)d_in[4];   // [2048,512]
    const float* b_ih   = (const float*)d_in[5];   // [2048]
    const float* b_hh   = (const float*)d_in[6];   // [2048]
    float* out = (float*)d_out;                    // out | hT | cT (fp32)

    const int smem_bytes = (64 * HS_STRIDE + 8 * RED_W + 1024) * 4;
    cudaFuncSetAttribute(lstm_kernel, cudaFuncAttributeMaxDynamicSharedMemorySize, smem_bytes);

    dim3 xg(GDIM / 128, (TSTEPS * BATCH) / 128);   // (16, 256)
    xproj_kernel<<<xg, 256>>>(inputs, W_ih, b_ih, b_hh);

    lstm_kernel<<<GRID_BLOCKS, 256, smem_bytes>>>(mask, h0, W_hh, out);
}

// round 9
// speedup vs baseline: 1.2809x; 1.2809x over previous
#include <cuda_runtime.h>
#include <cstdint>
#include <cstddef>

#define TSTEPS 512
#define BATCH  64
#define DIM    512
#define HID    512
#define GDIM   2048            // 4*HID
#define GRID_BLOCKS 64
#define JB 8                   // hidden columns per recurrent block
#define HS_STRIDE 516          // padded (512+4) to kill bank conflicts
#define RED_B 36               // padded partial row stride
#define RED_W (64 * RED_B)     // one warp's partial tile

// ---------------- scratch (static device allocations; no cudaMalloc) -------
__device__ float g_xproj[(size_t)TSTEPS * BATCH * GDIM];  // 256 MB: x@W_ih^T + bias
__device__ float g_hbuf[2][BATCH * HID];                  // ping-pong hidden state
// per-producer-BLOCK monotonic counters, padded to 32B sectors.
// counter for block blk lives at g_cnt2[blk*8]; value = 8*(1 + steps done).
__device__ unsigned g_cnt2[GRID_BLOCKS * 8];

// ---------------- helpers ---------------------------------------------------
__device__ __forceinline__ float tf32r(float x) {
    uint32_t r; asm("cvt.rna.tf32.f32 %0, %1;" : "=r"(r) : "f"(x));
    return __uint_as_float(r);
}
__device__ __forceinline__ void mma_tf32(float c[4], const uint32_t a[4], const uint32_t b[2]) {
    asm volatile(
        "mma.sync.aligned.m16n8k8.row.col.f32.tf32.tf32.f32 "
        "{%0,%1,%2,%3}, {%4,%5,%6,%7}, {%8,%9}, {%0,%1,%2,%3};"
        : "+f"(c[0]), "+f"(c[1]), "+f"(c[2]), "+f"(c[3])
        : "r"(a[0]), "r"(a[1]), "r"(a[2]), "r"(a[3]), "r"(b[0]), "r"(b[1]));
}
__device__ __forceinline__ float ex2f(float x) { float y; asm("ex2.approx.f32 %0, %1;" : "=f"(y) : "f"(x)); return y; }
__device__ __forceinline__ float rcpf(float x) { float y; asm("rcp.approx.f32 %0, %1;" : "=f"(y) : "f"(x)); return y; }
__device__ __forceinline__ float sigf(float x)  { return rcpf(1.0f + ex2f(-1.4426950408889634f * x)); }
__device__ __forceinline__ float tanhf_(float x){ return 2.0f * sigf(2.0f * x) - 1.0f; }

__device__ __forceinline__ unsigned ld_acq(const unsigned* p) {
    unsigned v; asm volatile("ld.acquire.gpu.global.u32 %0, [%1];" : "=r"(v) : "l"(p)); return v;
}
__device__ __forceinline__ void arrive_release(unsigned* p) {
    asm volatile("red.release.gpu.global.add.u32 [%0], 1;" :: "l"(p) : "memory");
}
__device__ __forceinline__ void cp16(uint32_t s, const void* g) {
    asm volatile("cp.async.cg.shared.global [%0], [%1], 16;" :: "r"(s), "l"(g));
}

// ============================================================================
// Kernel 1: x_proj[m, g] = sum_d X[m,d]*W_ih[g,d] + (b_ih[g]+b_hh[g])
// M = T*B = 32768, K = 512, N = 2048.  TF32 mma.sync, 128x128x32 tiles.
// Also resets the per-block counters for the lstm kernel that follows.
// ============================================================================
__global__ void __launch_bounds__(256) xproj_kernel(
    const float* __restrict__ X, const float* __restrict__ Wih,
    const float* __restrict__ b_ih, const float* __restrict__ b_hh)
{
    {
        int bid = blockIdx.y * gridDim.x + blockIdx.x;      // 0..4095
        if (threadIdx.x == 0 && bid < GRID_BLOCKS * 8) g_cnt2[bid] = 0u;
    }

    __shared__ float As[128][36];
    __shared__ float Bs[32][132];

    const int m0 = blockIdx.y * 128;
    const int n0 = blockIdx.x * 128;
    const int tid  = threadIdx.x;
    const int lane = tid & 31;
    const int warp = tid >> 5;
    const int wm = warp >> 1;       // 0..3 : 32 output rows each
    const int wn = warp & 1;        // 0..1 : 64 output cols each
    const int gid = lane >> 2;      // 0..7
    const int tig = lane & 3;       // 0..3

    float acc[2][8][4];
    #pragma unroll
    for (int mt = 0; mt < 2; mt++)
        #pragma unroll
        for (int nt = 0; nt < 8; nt++)
            #pragma unroll
            for (int q = 0; q < 4; q++) acc[mt][nt][q] = 0.0f;

    const int lr = tid >> 3;          // 0..31
    const int lc = (tid & 7) * 4;     // 0..28

    for (int k0 = 0; k0 < DIM; k0 += 32) {
        __syncthreads();
        #pragma unroll
        for (int p = 0; p < 4; p++) {
            int r = lr + p * 32;
            float4 v = *(const float4*)(X + (size_t)(m0 + r) * DIM + k0 + lc);
            As[r][lc+0] = tf32r(v.x); As[r][lc+1] = tf32r(v.y);
            As[r][lc+2] = tf32r(v.z); As[r][lc+3] = tf32r(v.w);
        }
        #pragma unroll
        for (int p = 0; p < 4; p++) {
            int n = lr + p * 32;
            float4 v = *(const float4*)(Wih + (size_t)(n0 + n) * DIM + k0 + lc);
            Bs[lc+0][n] = tf32r(v.x); Bs[lc+1][n] = tf32r(v.y);
            Bs[lc+2][n] = tf32r(v.z); Bs[lc+3][n] = tf32r(v.w);
        }
        __syncthreads();

        #pragma unroll
        for (int ks = 0; ks < 4; ks++) {
            const int kb = ks * 8;
            uint32_t a[2][4], b[8][2];
            #pragma unroll
            for (int mt = 0; mt < 2; mt++) {
                int row = wm * 32 + mt * 16;
                a[mt][0] = __float_as_uint(As[row + gid    ][kb + tig    ]);
                a[mt][1] = __float_as_uint(As[row + gid + 8][kb + tig    ]);
                a[mt][2] = __float_as_uint(As[row + gid    ][kb + tig + 4]);
                a[mt][3] = __float_as_uint(As[row + gid + 8][kb + tig + 4]);
            }
            #pragma unroll
            for (int nt = 0; nt < 8; nt++) {
                int col = wn * 64 + nt * 8 + gid;
                b[nt][0] = __float_as_uint(Bs[kb + tig    ][col]);
                b[nt][1] = __float_as_uint(Bs[kb + tig + 4][col]);
            }
            #pragma unroll
            for (int mt = 0; mt < 2; mt++)
                #pragma unroll
                for (int nt = 0; nt < 8; nt++)
                    mma_tf32(acc[mt][nt], a[mt], b[nt]);
        }
    }

    // epilogue: add bias, write fp32
    #pragma unroll
    for (int mt = 0; mt < 2; mt++) {
        #pragma unroll
        for (int nt = 0; nt < 8; nt++) {
            int row = m0 + wm * 32 + mt * 16 + gid;
            int col = n0 + wn * 64 + nt * 8 + 2 * tig;
            float bz0 = b_ih[col]     + b_hh[col];
            float bz1 = b_ih[col + 1] + b_hh[col + 1];
            float2 v0 = make_float2(acc[mt][nt][0] + bz0, acc[mt][nt][1] + bz1);
            float2 v1 = make_float2(acc[mt][nt][2] + bz0, acc[mt][nt][3] + bz1);
            *(float2*)(g_xproj + (size_t)row       * GDIM + col) = v0;
            *(float2*)(g_xproj + (size_t)(row + 8) * GDIM + col) = v1;
        }
    }
}

// ============================================================================
// Kernel 2: persistent recurrence = R4 structure + per-block counters +
// two-stage load/compute overlap.
// 64 blocks x 256 threads (8 warps). Block owns JB=8 hidden cols (32 gate
// cols); warp w owns K-slice [64w, 64w+64), B fragments register-resident.
// Sync: block blk's counter g_cnt2[blk*8] += 1 per warp per step (8/step).
// Consumer warp w polls the 8 counters of blocks 8w..8w+7 lane-parallel
// (lane reads counter of block 8w+(lane&7)), single ballot loop.
// Load: 32 cp16 split into two column-half commit groups; MMA k-chunks 0-3
// run after wait_group 1, hiding the second half's L2 latency.
// ============================================================================
__global__ void __launch_bounds__(256, 1) lstm_kernel(
    const float* __restrict__ mask, const float* __restrict__ h0,
    const float* __restrict__ Whh, float* __restrict__ out)
{
    extern __shared__ float smem[];
    float* h_s  = smem;                      // 64 x 516  (also W staging at init)
    float* red  = h_s  + 64 * HS_STRIDE;     // 8 x 64 x 36 partials
    float* h0_s = red  + 8 * RED_W;          // 512
    float* c_s  = h0_s + 512;                // 512

    const int tid  = threadIdx.x;
    const int blk  = blockIdx.x;
    const int j0   = blk * JB;
    const int lane = tid & 31;
    const int warp = tid >> 5;               // 0..7 -> K-slice
    const int gid  = lane >> 2;              // 0..7
    const int tig  = lane & 3;               // 0..3
    const int kbase = warp * 64;

    // --- stage W_hh slice (32 rows x 512) into h_s temporarily, as tf32
    for (int i = tid; i < 32 * 128; i += 256) {
        int r  = i >> 7;                 // 0..31  (gate*8 + jl)
        int k4 = (i & 127) * 4;
        int gate = r >> 3, jl = r & 7;
        float4 v = *(const float4*)(Whh + (size_t)(gate * HID + j0 + jl) * HID + k4);
        float* d = &h_s[r * HS_STRIDE + k4];
        d[0] = tf32r(v.x); d[1] = tf32r(v.y); d[2] = tf32r(v.z); d[3] = tf32r(v.w);
    }
    // --- h0 slice, c0 = h0; publish tf32-rounded h0 to ping buffer 0
    for (int i = tid; i < 512; i += 256) {
        int b = i >> 3, jl = i & 7;
        float v = h0[b * HID + j0 + jl];
        h0_s[i] = v;
        c_s[i]  = v;
        g_hbuf[0][b * HID + j0 + jl] = tf32r(v);
    }
    __syncthreads();

    // --- preload this warp's B fragments: b[kk][nt][2], resident forever
    uint32_t breg[8][4][2];
    #pragma unroll
    for (int kk = 0; kk < 8; kk++)
        #pragma unroll
        for (int nt = 0; nt < 4; nt++) {
            const float* pb = &h_s[(nt * 8 + gid) * HS_STRIDE + kbase + kk * 8 + tig];
            breg[kk][nt][0] = __float_as_uint(pb[0]);
            breg[kk][nt][1] = __float_as_uint(pb[4]);
        }
    __syncthreads();
    // h0 published (+1 per warp; counter reaches 8 = 8*(0+1))
    if (lane == 0) arrive_release(&g_cnt2[blk * 8]);

    const int rb  = tid >> 2;          // 0..63 batch row for reduce phase
    const int jl0 = (tid & 3) * 2;     // 0,2,4,6

    const uint32_t hss = (uint32_t)__cvta_generic_to_shared(h_s);
    // poll address for this warp+lane: counter of block 8*warp + (lane&7)
    const unsigned* pollp = &g_cnt2[(warp * 8 + (lane & 7)) * 8];

    // prefetch x_proj + mask for t=0
    const float* xp0 = g_xproj + (size_t)rb * GDIM + j0 + jl0;
    float2 xq[4];
    #pragma unroll
    for (int g = 0; g < 4; g++) xq[g] = *(const float2*)(xp0 + g * HID);
    float mval = mask[rb];

    for (int t = 0; t < TSTEPS; t++) {
        const float* hin  = g_hbuf[t & 1];
        float*       hout = g_hbuf[(t + 1) & 1];

        // ---- poll the 8 producer counters lane-parallel (one ballot loop)
        {
            const unsigned want = 8u * (unsigned)(t + 1);
            for (;;) {
                unsigned cv = ld_acq(pollp);
                if (__all_sync(0xffffffffu, cv >= want)) break;
            }
        }

        // ---- per-warp cp.async of K-slice in TWO column-half groups
        // group g covers cols [kbase + g*32, kbase + g*32 + 32), all 64 rows
        #pragma unroll
        for (int g = 0; g < 2; g++) {
            #pragma unroll 4
            for (int it = 0; it < 16; it++) {
                int e   = it * 32 + lane;          // 0..511
                int row = e >> 3;                  // 0..63
                int c4  = ((e & 7) << 2) + g * 32; // 0..28 (+32)
                cp16(hss + (uint32_t)(row * HS_STRIDE + kbase + c4) * 4,
                     hin + (size_t)row * HID + kbase + c4);
            }
            asm volatile("cp.async.commit_group;" ::: "memory");
        }

        // ---- split-K MMA in two halves, overlapping the second load group
        float acc[4][4][4];
        #pragma unroll
        for (int mt = 0; mt < 4; mt++)
            #pragma unroll
            for (int nt = 0; nt < 4; nt++)
                #pragma unroll
                for (int q = 0; q < 4; q++) acc[mt][nt][q] = 0.0f;

#define DO_HALF(K0, PEND)                                                       \
        {                                                                       \
            asm volatile("cp.async.wait_group " #PEND ";" ::: "memory");        \
            __syncwarp();                                                       \
            _Pragma("unroll")                                                   \
            for (int kk = (K0); kk < (K0) + 4; kk++) {                          \
                uint32_t a[4][4];                                               \
                _Pragma("unroll")                                               \
                for (int mt = 0; mt < 4; mt++) {                                \
                    const float* pa = &h_s[(mt * 16 + gid) * HS_STRIDE          \
                                           + kbase + kk * 8 + tig];             \
                    a[mt][0] = __float_as_uint(pa[0]);                          \
                    a[mt][1] = __float_as_uint(pa[8 * HS_STRIDE]);              \
                    a[mt][2] = __float_as_uint(pa[4]);                          \
                    a[mt][3] = __float_as_uint(pa[8 * HS_STRIDE + 4]);          \
                }                                                               \
                _Pragma("unroll")                                               \
                for (int mt = 0; mt < 4; mt++)                                  \
                    _Pragma("unroll")                                           \
                    for (int nt = 0; nt < 4; nt++)                              \
                        mma_tf32(acc[mt][nt], a[mt], breg[kk][nt]);             \
            }                                                                   \
        }
        DO_HALF(0, 1)
        DO_HALF(4, 0)
#undef DO_HALF

        // ---- store partials: red[warp][row][col]
        float* rw = red + warp * RED_W;
        #pragma unroll
        for (int mt = 0; mt < 4; mt++)
            #pragma unroll
            for (int nt = 0; nt < 4; nt++) {
                int row = mt * 16 + gid;
                int col = nt * 8 + 2 * tig;
                float* rp = &rw[row * RED_B + col];
                *(float2*)rp                 = make_float2(acc[mt][nt][0], acc[mt][nt][1]);
                *(float2*)(rp + 8 * RED_B)   = make_float2(acc[mt][nt][2], acc[mt][nt][3]);
            }
        __syncthreads();                       // bar A: partials complete

        // ---- reduce 8 partials + x_proj, LSTM cell, mask blend, publish h
        float s[4][2];
        #pragma unroll
        for (int g = 0; g < 4; g++) { s[g][0] = xq[g].x; s[g][1] = xq[g].y; }
        #pragma unroll
        for (int w = 0; w < 8; w++) {
            const float* rr = red + w * RED_W + rb * RED_B + jl0;
            #pragma unroll
            for (int g = 0; g < 4; g++) {
                float2 v = *(const float2*)(rr + g * 8);
                s[g][0] += v.x; s[g][1] += v.y;
            }
        }
        float hv[2], cv[2];
        #pragma unroll
        for (int u = 0; u < 2; u++) {
            float iv = sigf(s[0][u]);
            float fv = sigf(s[1][u]);
            float gv = tanhf_(s[2][u]);
            float ov = sigf(s[3][u]);
            int p = rb * 8 + jl0 + u;
            float c = fv * c_s[p] + iv * gv;
            float h = ov * tanhf_(c);
            float z = h0_s[p];                   // h0 == c0
            h = h * mval + z * (1.0f - mval);
            c = c * mval + z * (1.0f - mval);
            c_s[p] = c;
            hv[u] = h; cv[u] = c;
            hout[rb * HID + j0 + jl0 + u] = tf32r(h);
        }
        // this warp's hout rows stored -> release-arrive (+1 of 8 per block)
        __syncwarp();
        if (lane == 0) arrive_release(&g_cnt2[blk * 8]);

        // ---- shadow: out[] stores + next-step prefetch (off critical path)
        #pragma unroll
        for (int u = 0; u < 2; u++) {
            int gcol = j0 + jl0 + u;
            out[(size_t)t * BATCH * HID + rb * HID + gcol] = hv[u];
            if (t == TSTEPS - 1) {
                out[(size_t)TSTEPS * BATCH * HID               + rb * HID + gcol] = hv[u];
                out[(size_t)TSTEPS * BATCH * HID + BATCH * HID + rb * HID + gcol] = cv[u];
            }
        }
        if (t + 1 < TSTEPS) {
            const float* xp = g_xproj + (size_t)(t + 1) * BATCH * GDIM
                            + (size_t)rb * GDIM + j0 + jl0;
            #pragma unroll
            for (int g = 0; g < 4; g++) xq[g] = *(const float2*)(xp + g * HID);
            mval = mask[(t + 1) * BATCH + rb];
        }
        __syncthreads();                       // bar B: red safe to overwrite
    }
}

// ============================================================================
extern "C" void kernel_launch(void* const* d_in, const int* in_sizes, int n_in,
                              void* d_out, int out_size) {
    const float* inputs = (const float*)d_in[0];   // [512,64,512]
    const float* mask   = (const float*)d_in[1];   // [512,64]
    const float* h0     = (const float*)d_in[2];   // [64,512]
    const float* W_ih   = (const float*)d_in[3];   // [2048,512]
    const float* W_hh   = (const float*)d_in[4];   // [2048,512]
    const float* b_ih   = (const float*)d_in[5];   // [2048]
    const float* b_hh   = (const float*)d_in[6];   // [2048]
    float* out = (float*)d_out;                    // out | hT | cT (fp32)

    const int smem_bytes = (64 * HS_STRIDE + 8 * RED_W + 1024) * 4;
    cudaFuncSetAttribute(lstm_kernel, cudaFuncAttributeMaxDynamicSharedMemorySize, smem_bytes);

    dim3 xg(GDIM / 128, (TSTEPS * BATCH) / 128);   // (16, 256)
    xproj_kernel<<<xg, 256>>>(inputs, W_ih, b_ih, b_hh);

    lstm_kernel<<<GRID_BLOCKS, 256, smem_bytes>>>(mask, h0, W_hh, out);
}

// round 10
// speedup vs baseline: 1.5050x; 1.1750x over previous
#include <cuda_runtime.h>
#include <cstdint>
#include <cstddef>

#define TSTEPS 512
#define BATCH  64
#define DIM    512
#define HID    512
#define GDIM   2048            // 4*HID
#define GRID_BLOCKS 64
#define JB 8                   // hidden columns per recurrent block
#define HS_STRIDE 520          // padded (512+8): conflict-free LDS.64
#define RED_B 36               // padded partial row stride
#define RED_W (64 * RED_B)     // one K-group's partial tile
#define NKW 4                  // split-K groups

// permute within each 8-col group: cols {t, t+4} become adjacent pair
__host__ __device__ __forceinline__ int pjmap(int jl) { return 2 * (jl & 3) + (jl >> 2); }

// ---------------- scratch (static device allocations; no cudaMalloc) -------
__device__ float g_xproj[(size_t)TSTEPS * BATCH * GDIM];  // 256 MB: x@W_ih^T + bias
__device__ float g_hbuf[2][BATCH * HID];                  // ping-pong hidden (PERMUTED cols)
// per-producer-BLOCK monotonic counters, padded to 32B sectors.
__device__ unsigned g_cnt2[GRID_BLOCKS * 8];

// ---------------- helpers ---------------------------------------------------
__device__ __forceinline__ float tf32r(float x) {
    uint32_t r; asm("cvt.rna.tf32.f32 %0, %1;" : "=r"(r) : "f"(x));
    return __uint_as_float(r);
}
__device__ __forceinline__ void mma_tf32(float c[4], const uint32_t a[4], const uint32_t b[2]) {
    asm volatile(
        "mma.sync.aligned.m16n8k8.row.col.f32.tf32.tf32.f32 "
        "{%0,%1,%2,%3}, {%4,%5,%6,%7}, {%8,%9}, {%0,%1,%2,%3};"
        : "+f"(c[0]), "+f"(c[1]), "+f"(c[2]), "+f"(c[3])
        : "r"(a[0]), "r"(a[1]), "r"(a[2]), "r"(a[3]), "r"(b[0]), "r"(b[1]));
}
__device__ __forceinline__ float ex2f(float x) { float y; asm("ex2.approx.f32 %0, %1;" : "=f"(y) : "f"(x)); return y; }
__device__ __forceinline__ float rcpf(float x) { float y; asm("rcp.approx.f32 %0, %1;" : "=f"(y) : "f"(x)); return y; }
__device__ __forceinline__ float sigf(float x)  { return rcpf(1.0f + ex2f(-1.4426950408889634f * x)); }
__device__ __forceinline__ float tanhf_(float x){ return 2.0f * sigf(2.0f * x) - 1.0f; }

__device__ __forceinline__ unsigned ld_acq(const unsigned* p) {
    unsigned v; asm volatile("ld.acquire.gpu.global.u32 %0, [%1];" : "=r"(v) : "l"(p)); return v;
}
__device__ __forceinline__ void arrive_release(unsigned* p) {
    asm volatile("red.release.gpu.global.add.u32 [%0], 1;" :: "l"(p) : "memory");
}
__device__ __forceinline__ void cp16(uint32_t s, const void* g) {
    asm volatile("cp.async.cg.shared.global [%0], [%1], 16;" :: "r"(s), "l"(g));
}

// ============================================================================
// Kernel 1: x_proj = X @ W_ih^T + bias (TF32 mma, 128x128x32 tiles) +
// counter reset for the recurrence kernel.
// ============================================================================
__global__ void __launch_bounds__(256) xproj_kernel(
    const float* __restrict__ X, const float* __restrict__ Wih,
    const float* __restrict__ b_ih, const float* __restrict__ b_hh)
{
    {
        int bid = blockIdx.y * gridDim.x + blockIdx.x;      // 0..4095
        if (threadIdx.x == 0 && bid < GRID_BLOCKS * 8) g_cnt2[bid] = 0u;
    }

    __shared__ float As[128][36];
    __shared__ float Bs[32][132];

    const int m0 = blockIdx.y * 128;
    const int n0 = blockIdx.x * 128;
    const int tid  = threadIdx.x;
    const int lane = tid & 31;
    const int warp = tid >> 5;
    const int wm = warp >> 1;
    const int wn = warp & 1;
    const int gid = lane >> 2;
    const int tig = lane & 3;

    float acc[2][8][4];
    #pragma unroll
    for (int mt = 0; mt < 2; mt++)
        #pragma unroll
        for (int nt = 0; nt < 8; nt++)
            #pragma unroll
            for (int q = 0; q < 4; q++) acc[mt][nt][q] = 0.0f;

    const int lr = tid >> 3;
    const int lc = (tid & 7) * 4;

    for (int k0 = 0; k0 < DIM; k0 += 32) {
        __syncthreads();
        #pragma unroll
        for (int p = 0; p < 4; p++) {
            int r = lr + p * 32;
            float4 v = *(const float4*)(X + (size_t)(m0 + r) * DIM + k0 + lc);
            As[r][lc+0] = tf32r(v.x); As[r][lc+1] = tf32r(v.y);
            As[r][lc+2] = tf32r(v.z); As[r][lc+3] = tf32r(v.w);
        }
        #pragma unroll
        for (int p = 0; p < 4; p++) {
            int n = lr + p * 32;
            float4 v = *(const float4*)(Wih + (size_t)(n0 + n) * DIM + k0 + lc);
            Bs[lc+0][n] = tf32r(v.x); Bs[lc+1][n] = tf32r(v.y);
            Bs[lc+2][n] = tf32r(v.z); Bs[lc+3][n] = tf32r(v.w);
        }
        __syncthreads();

        #pragma unroll
        for (int ks = 0; ks < 4; ks++) {
            const int kb = ks * 8;
            uint32_t a[2][4], b[8][2];
            #pragma unroll
            for (int mt = 0; mt < 2; mt++) {
                int row = wm * 32 + mt * 16;
                a[mt][0] = __float_as_uint(As[row + gid    ][kb + tig    ]);
                a[mt][1] = __float_as_uint(As[row + gid + 8][kb + tig    ]);
                a[mt][2] = __float_as_uint(As[row + gid    ][kb + tig + 4]);
                a[mt][3] = __float_as_uint(As[row + gid + 8][kb + tig + 4]);
            }
            #pragma unroll
            for (int nt = 0; nt < 8; nt++) {
                int col = wn * 64 + nt * 8 + gid;
                b[nt][0] = __float_as_uint(Bs[kb + tig    ][col]);
                b[nt][1] = __float_as_uint(Bs[kb + tig + 4][col]);
            }
            #pragma unroll
            for (int mt = 0; mt < 2; mt++)
                #pragma unroll
                for (int nt = 0; nt < 8; nt++)
                    mma_tf32(acc[mt][nt], a[mt], b[nt]);
        }
    }

    #pragma unroll
    for (int mt = 0; mt < 2; mt++) {
        #pragma unroll
        for (int nt = 0; nt < 8; nt++) {
            int row = m0 + wm * 32 + mt * 16 + gid;
            int col = n0 + wn * 64 + nt * 8 + 2 * tig;
            float bz0 = b_ih[col]     + b_hh[col];
            float bz1 = b_ih[col + 1] + b_hh[col + 1];
            float2 v0 = make_float2(acc[mt][nt][0] + bz0, acc[mt][nt][1] + bz1);
            float2 v1 = make_float2(acc[mt][nt][2] + bz0, acc[mt][nt][3] + bz1);
            *(float2*)(g_xproj + (size_t)row       * GDIM + col) = v0;
            *(float2*)(g_xproj + (size_t)(row + 8) * GDIM + col) = v1;
        }
    }
}

// ============================================================================
// Kernel 2: persistent recurrence. Split-K 4 x split-M 2, register-resident
// W_hh (breg[16][4][2]), PERMUTED h storage so A-fragments load as LDS.64
// pairs, per-block counters, two-stage cp.async/MMA overlap.
// Warp (kw = warp&3, mh = warp>>2): rows [32mh,32mh+32), K [128kw,128kw+128).
// Consumer kw polls blocks 16kw..16kw+15 lane-parallel. Partials in red[4].
// ============================================================================
__global__ void __launch_bounds__(256, 1) lstm_kernel(
    const float* __restrict__ mask, const float* __restrict__ h0,
    const float* __restrict__ Whh, float* __restrict__ out)
{
    extern __shared__ float smem[];
    float* h_s  = smem;                      // 64 x 520 (also W staging at init)
    float* red  = h_s  + 64 * HS_STRIDE;     // 4 x 64 x 36 partials
    float* h0_s = red  + NKW * RED_W;        // 512
    float* c_s  = h0_s + 512;                // 512

    const int tid  = threadIdx.x;
    const int blk  = blockIdx.x;
    const int j0   = blk * JB;
    const int lane = tid & 31;
    const int warp = tid >> 5;
    const int kw   = warp & 3;               // K-group 0..3
    const int mh   = warp >> 2;              // m-half 0..1
    const int gid  = lane >> 2;
    const int tig  = lane & 3;
    const int kbase = kw * 128;

    // --- stage W_hh slice (32 rows x 512) into h_s temporarily, as tf32
    for (int i = tid; i < 32 * 128; i += 256) {
        int r  = i >> 7;
        int k4 = (i & 127) * 4;
        int gate = r >> 3, jl = r & 7;
        float4 v = *(const float4*)(Whh + (size_t)(gate * HID + j0 + jl) * HID + k4);
        float* d = &h_s[r * HS_STRIDE + k4];
        d[0] = tf32r(v.x); d[1] = tf32r(v.y); d[2] = tf32r(v.z); d[3] = tf32r(v.w);
    }
    // --- h0 slice, c0 = h0; publish tf32-rounded h0 to ping buffer 0, PERMUTED
    for (int i = tid; i < 512; i += 256) {
        int b = i >> 3, jl = i & 7;
        float v = h0[b * HID + j0 + jl];
        h0_s[i] = v;
        c_s[i]  = v;
        g_hbuf[0][b * HID + j0 + pjmap(jl)] = tf32r(v);
    }
    __syncthreads();

    // --- preload this warp's B fragments: breg[16][4][2], resident forever
    uint32_t breg[16][4][2];
    #pragma unroll
    for (int kk = 0; kk < 16; kk++)
        #pragma unroll
        for (int nt = 0; nt < 4; nt++) {
            const float* pb = &h_s[(nt * 8 + gid) * HS_STRIDE + kbase + kk * 8 + tig];
            breg[kk][nt][0] = __float_as_uint(pb[0]);
            breg[kk][nt][1] = __float_as_uint(pb[4]);
        }
    __syncthreads();
    // h0 published (+1 per warp; counter reaches 8)
    if (lane == 0) arrive_release(&g_cnt2[blk * 8]);

    const int rb  = tid >> 2;          // 0..63 batch row for reduce phase
    const int jl0 = (tid & 3) * 2;     // 0,2,4,6

    const uint32_t hss = (uint32_t)__cvta_generic_to_shared(h_s);
    // poll: counter of block 16*kw + (lane&15)
    const unsigned* pollp = &g_cnt2[(kw * 16 + (lane & 15)) * 8];

    // prefetch x_proj + mask for t=0
    const float* xp0 = g_xproj + (size_t)rb * GDIM + j0 + jl0;
    float2 xq[4];
    #pragma unroll
    for (int g = 0; g < 4; g++) xq[g] = *(const float2*)(xp0 + g * HID);
    float mval = mask[rb];

    for (int t = 0; t < TSTEPS; t++) {
        const float* hin  = g_hbuf[t & 1];
        float*       hout = g_hbuf[(t + 1) & 1];

        // ---- poll 16 producer counters lane-parallel (one ballot loop)
        {
            const unsigned want = 8u * (unsigned)(t + 1);
            for (;;) {
                unsigned cv = ld_acq(pollp);
                if (__all_sync(0xffffffffu, cv >= want)) break;
            }
        }

        // ---- cp.async rows [32mh,+32) x cols [kbase,+128) in TWO col halves
        #pragma unroll
        for (int g = 0; g < 2; g++) {
            #pragma unroll 4
            for (int it = 0; it < 16; it++) {
                int e    = it * 32 + lane;            // 0..511
                int row  = 32 * mh + (e >> 4);        // 32 rows
                int c4   = ((e & 15) << 2) + g * 64;  // 64 cols per half
                cp16(hss + (uint32_t)(row * HS_STRIDE + kbase + c4) * 4,
                     hin + (size_t)row * HID + kbase + c4);
            }
            asm volatile("cp.async.commit_group;" ::: "memory");
        }

        // ---- split-K MMA in two halves (LDS.64 A pairs from permuted layout)
        float acc[2][4][4];
        #pragma unroll
        for (int mt = 0; mt < 2; mt++)
            #pragma unroll
            for (int nt = 0; nt < 4; nt++)
                #pragma unroll
                for (int q = 0; q < 4; q++) acc[mt][nt][q] = 0.0f;

#define DO_HALF(K0, PEND)                                                       \
        {                                                                       \
            asm volatile("cp.async.wait_group " #PEND ";" ::: "memory");        \
            __syncwarp();                                                       \
            _Pragma("unroll")                                                   \
            for (int kk = (K0); kk < (K0) + 8; kk++) {                          \
                uint32_t a[2][4];                                               \
                _Pragma("unroll")                                               \
                for (int mt = 0; mt < 2; mt++) {                                \
                    int row = 32 * mh + mt * 16 + gid;                          \
                    float2 v0 = *(const float2*)&h_s[row * HS_STRIDE            \
                                      + kbase + kk * 8 + 2 * tig];              \
                    float2 v1 = *(const float2*)&h_s[(row + 8) * HS_STRIDE      \
                                      + kbase + kk * 8 + 2 * tig];              \
                    a[mt][0] = __float_as_uint(v0.x);                           \
                    a[mt][1] = __float_as_uint(v1.x);                           \
                    a[mt][2] = __float_as_uint(v0.y);                           \
                    a[mt][3] = __float_as_uint(v1.y);                           \
                }                                                               \
                _Pragma("unroll")                                               \
                for (int mt = 0; mt < 2; mt++)                                  \
                    _Pragma("unroll")                                           \
                    for (int nt = 0; nt < 4; nt++)                              \
                        mma_tf32(acc[mt][nt], a[mt], breg[kk][nt]);             \
            }                                                                   \
        }
        DO_HALF(0, 1)
        DO_HALF(8, 0)
#undef DO_HALF

        // ---- store partials: red[kw][row][col], rows 32mh..32mh+32
        float* rw = red + kw * RED_W;
        #pragma unroll
        for (int mt = 0; mt < 2; mt++)
            #pragma unroll
            for (int nt = 0; nt < 4; nt++) {
                int row = 32 * mh + mt * 16 + gid;
                int col = nt * 8 + 2 * tig;
                float* rp = &rw[row * RED_B + col];
                *(float2*)rp                 = make_float2(acc[mt][nt][0], acc[mt][nt][1]);
                *(float2*)(rp + 8 * RED_B)   = make_float2(acc[mt][nt][2], acc[mt][nt][3]);
            }
        __syncthreads();                       // bar A: partials complete

        // ---- reduce 4 partials + x_proj, LSTM cell, mask blend, publish h
        float s[4][2];
        #pragma unroll
        for (int g = 0; g < 4; g++) { s[g][0] = xq[g].x; s[g][1] = xq[g].y; }
        #pragma unroll
        for (int w = 0; w < NKW; w++) {
            const float* rr = red + w * RED_W + rb * RED_B + jl0;
            #pragma unroll
            for (int g = 0; g < 4; g++) {
                float2 v = *(const float2*)(rr + g * 8);
                s[g][0] += v.x; s[g][1] += v.y;
            }
        }
        float hv[2], cv[2];
        #pragma unroll
        for (int u = 0; u < 2; u++) {
            float iv = sigf(s[0][u]);
            float fv = sigf(s[1][u]);
            float gv = tanhf_(s[2][u]);
            float ov = sigf(s[3][u]);
            int p = rb * 8 + jl0 + u;
            float c = fv * c_s[p] + iv * gv;
            float h = ov * tanhf_(c);
            float z = h0_s[p];                   // h0 == c0
            h = h * mval + z * (1.0f - mval);
            c = c * mval + z * (1.0f - mval);
            c_s[p] = c;
            hv[u] = h; cv[u] = c;
            hout[rb * HID + j0 + pjmap(jl0 + u)] = tf32r(h);   // PERMUTED
        }
        // this warp's hout rows (8w..8w+7) stored -> release-arrive
        __syncwarp();
        if (lane == 0) arrive_release(&g_cnt2[blk * 8]);

        // ---- shadow: out[] stores + next-step prefetch (off critical path)
        #pragma unroll
        for (int u = 0; u < 2; u++) {
            int gcol = j0 + jl0 + u;                          // UNPERMUTED
            out[(size_t)t * BATCH * HID + rb * HID + gcol] = hv[u];
            if (t == TSTEPS - 1) {
                out[(size_t)TSTEPS * BATCH * HID               + rb * HID + gcol] = hv[u];
                out[(size_t)TSTEPS * BATCH * HID + BATCH * HID + rb * HID + gcol] = cv[u];
            }
        }
        if (t + 1 < TSTEPS) {
            const float* xp = g_xproj + (size_t)(t + 1) * BATCH * GDIM
                            + (size_t)rb * GDIM + j0 + jl0;
            #pragma unroll
            for (int g = 0; g < 4; g++) xq[g] = *(const float2*)(xp + g * HID);
            mval = mask[(t + 1) * BATCH + rb];
        }
        __syncthreads();                       // bar B: red safe to overwrite
    }
}

// ============================================================================
extern "C" void kernel_launch(void* const* d_in, const int* in_sizes, int n_in,
                              void* d_out, int out_size) {
    const float* inputs = (const float*)d_in[0];   // [512,64,512]
    const float* mask   = (const float*)d_in[1];   // [512,64]
    const float* h0     = (const float*)d_in[2];   // [64,512]
    const float* W_ih   = (const float*)d_in[3];   // [2048,512]
    const float* W_hh   = (const float*)d_in[4];   // [2048,512]
    const float* b_ih   = (const float*)d_in[5];   // [2048]
    const float* b_hh   = (const float*)d_in[6];   // [2048]
    float* out = (float*)d_out;                    // out | hT | cT (fp32)

    const int smem_bytes = (64 * HS_STRIDE + NKW * RED_W + 1024) * 4;
    cudaFuncSetAttribute(lstm_kernel, cudaFuncAttributeMaxDynamicSharedMemorySize, smem_bytes);

    dim3 xg(GDIM / 128, (TSTEPS * BATCH) / 128);   // (16, 256)
    xproj_kernel<<<xg, 256>>>(inputs, W_ih, b_ih, b_hh);

    lstm_kernel<<<GRID_BLOCKS, 256, smem_bytes>>>(mask, h0, W_hh, out);
}

// round 11
// speedup vs baseline: 1.8943x; 1.2587x over previous
#include <cuda_runtime.h>
#include <cstdint>
#include <cstddef>

#define TSTEPS 512
#define BATCH  64
#define DIM    512
#define HID    512
#define GDIM   2048            // 4*HID
#define LSTM_BLOCKS 128        // (2 batch halves) x (64 j-column blocks)
#define BROWS 32               // batch rows per block
#define JB 8                   // hidden columns per recurrent block
#define HS_STRIDE 520          // padded (512+8): conflict-free LDS.64
#define RED_B 36               // padded partial row stride
#define RED_W (BROWS * RED_B)  // one K-group's partial tile
#define NKW 4                  // split-K groups

// permute within each 8-col group: cols {t, t+4} become adjacent pair
__host__ __device__ __forceinline__ int pjmap(int jl) { return 2 * (jl & 3) + (jl >> 2); }

// ---------------- scratch (static device allocations; no cudaMalloc) -------
__device__ float g_xproj[(size_t)TSTEPS * BATCH * GDIM];  // 256 MB: x@W_ih^T + bias
__device__ float g_hbuf[2][BATCH * HID];                  // ping-pong hidden (PERMUTED cols)
// per-producer-BLOCK monotonic counters, padded to 32B sectors.
__device__ unsigned g_cnt2[LSTM_BLOCKS * 8];

// ---------------- helpers ---------------------------------------------------
__device__ __forceinline__ float tf32r(float x) {
    uint32_t r; asm("cvt.rna.tf32.f32 %0, %1;" : "=r"(r) : "f"(x));
    return __uint_as_float(r);
}
__device__ __forceinline__ void mma_tf32(float c[4], const uint32_t a[4], const uint32_t b[2]) {
    asm volatile(
        "mma.sync.aligned.m16n8k8.row.col.f32.tf32.tf32.f32 "
        "{%0,%1,%2,%3}, {%4,%5,%6,%7}, {%8,%9}, {%0,%1,%2,%3};"
        : "+f"(c[0]), "+f"(c[1]), "+f"(c[2]), "+f"(c[3])
        : "r"(a[0]), "r"(a[1]), "r"(a[2]), "r"(a[3]), "r"(b[0]), "r"(b[1]));
}
__device__ __forceinline__ float ex2f(float x) { float y; asm("ex2.approx.f32 %0, %1;" : "=f"(y) : "f"(x)); return y; }
__device__ __forceinline__ float rcpf(float x) { float y; asm("rcp.approx.f32 %0, %1;" : "=f"(y) : "f"(x)); return y; }
__device__ __forceinline__ float sigf(float x)  { return rcpf(1.0f + ex2f(-1.4426950408889634f * x)); }
__device__ __forceinline__ float tanhf_(float x){ return 2.0f * sigf(2.0f * x) - 1.0f; }

__device__ __forceinline__ unsigned ld_acq(const unsigned* p) {
    unsigned v; asm volatile("ld.acquire.gpu.global.u32 %0, [%1];" : "=r"(v) : "l"(p)); return v;
}
__device__ __forceinline__ void arrive_release(unsigned* p) {
    asm volatile("red.release.gpu.global.add.u32 [%0], 1;" :: "l"(p) : "memory");
}
__device__ __forceinline__ void cp16(uint32_t s, const void* g) {
    asm volatile("cp.async.cg.shared.global [%0], [%1], 16;" :: "r"(s), "l"(g));
}

// ============================================================================
// Kernel 1: x_proj = X @ W_ih^T + bias (TF32 mma, 128x128x32 tiles) +
// counter reset for the recurrence kernel.
// ============================================================================
__global__ void __launch_bounds__(256) xproj_kernel(
    const float* __restrict__ X, const float* __restrict__ Wih,
    const float* __restrict__ b_ih, const float* __restrict__ b_hh)
{
    {
        int bid = blockIdx.y * gridDim.x + blockIdx.x;      // 0..4095
        if (threadIdx.x == 0 && bid < LSTM_BLOCKS * 8) g_cnt2[bid] = 0u;
    }

    __shared__ float As[128][36];
    __shared__ float Bs[32][132];

    const int m0 = blockIdx.y * 128;
    const int n0 = blockIdx.x * 128;
    const int tid  = threadIdx.x;
    const int lane = tid & 31;
    const int warp = tid >> 5;
    const int wm = warp >> 1;
    const int wn = warp & 1;
    const int gid = lane >> 2;
    const int tig = lane & 3;

    float acc[2][8][4];
    #pragma unroll
    for (int mt = 0; mt < 2; mt++)
        #pragma unroll
        for (int nt = 0; nt < 8; nt++)
            #pragma unroll
            for (int q = 0; q < 4; q++) acc[mt][nt][q] = 0.0f;

    const int lr = tid >> 3;
    const int lc = (tid & 7) * 4;

    for (int k0 = 0; k0 < DIM; k0 += 32) {
        __syncthreads();
        #pragma unroll
        for (int p = 0; p < 4; p++) {
            int r = lr + p * 32;
            float4 v = *(const float4*)(X + (size_t)(m0 + r) * DIM + k0 + lc);
            As[r][lc+0] = tf32r(v.x); As[r][lc+1] = tf32r(v.y);
            As[r][lc+2] = tf32r(v.z); As[r][lc+3] = tf32r(v.w);
        }
        #pragma unroll
        for (int p = 0; p < 4; p++) {
            int n = lr + p * 32;
            float4 v = *(const float4*)(Wih + (size_t)(n0 + n) * DIM + k0 + lc);
            Bs[lc+0][n] = tf32r(v.x); Bs[lc+1][n] = tf32r(v.y);
            Bs[lc+2][n] = tf32r(v.z); Bs[lc+3][n] = tf32r(v.w);
        }
        __syncthreads();

        #pragma unroll
        for (int ks = 0; ks < 4; ks++) {
            const int kb = ks * 8;
            uint32_t a[2][4], b[8][2];
            #pragma unroll
            for (int mt = 0; mt < 2; mt++) {
                int row = wm * 32 + mt * 16;
                a[mt][0] = __float_as_uint(As[row + gid    ][kb + tig    ]);
                a[mt][1] = __float_as_uint(As[row + gid + 8][kb + tig    ]);
                a[mt][2] = __float_as_uint(As[row + gid    ][kb + tig + 4]);
                a[mt][3] = __float_as_uint(As[row + gid + 8][kb + tig + 4]);
            }
            #pragma unroll
            for (int nt = 0; nt < 8; nt++) {
                int col = wn * 64 + nt * 8 + gid;
                b[nt][0] = __float_as_uint(Bs[kb + tig    ][col]);
                b[nt][1] = __float_as_uint(Bs[kb + tig + 4][col]);
            }
            #pragma unroll
            for (int mt = 0; mt < 2; mt++)
                #pragma unroll
                for (int nt = 0; nt < 8; nt++)
                    mma_tf32(acc[mt][nt], a[mt], b[nt]);
        }
    }

    #pragma unroll
    for (int mt = 0; mt < 2; mt++) {
        #pragma unroll
        for (int nt = 0; nt < 8; nt++) {
            int row = m0 + wm * 32 + mt * 16 + gid;
            int col = n0 + wn * 64 + nt * 8 + 2 * tig;
            float bz0 = b_ih[col]     + b_hh[col];
            float bz1 = b_ih[col + 1] + b_hh[col + 1];
            float2 v0 = make_float2(acc[mt][nt][0] + bz0, acc[mt][nt][1] + bz1);
            float2 v1 = make_float2(acc[mt][nt][2] + bz0, acc[mt][nt][3] + bz1);
            *(float2*)(g_xproj + (size_t)row       * GDIM + col) = v0;
            *(float2*)(g_xproj + (size_t)(row + 8) * GDIM + col) = v1;
        }
    }
}

// ============================================================================
// Kernel 2: persistent recurrence. 128 blocks = (2 batch halves bb) x
// (64 j-blocks jb). Batch rows are independent in an LSTM, so the two halves
// form decoupled dependency chains. Block owns rows [32bb,+32) x gate cols
// for j in [8jb,+8). Warp (kw=warp&3, mh=warp>>2): local rows [16mh,+16),
// K cols [128kw,+128); W_hh B-fragments register-resident (breg[16][4][2]).
// Permuted h layout -> LDS.64 A pairs; per-block counters (8 arrivals);
// consumer warp kw polls the 16 same-half producers 16kw..16kw+15.
// ============================================================================
__global__ void __launch_bounds__(256, 1) lstm_kernel(
    const float* __restrict__ mask, const float* __restrict__ h0,
    const float* __restrict__ Whh, float* __restrict__ out)
{
    extern __shared__ float smem[];
    float* h_s  = smem;                      // 32 x 520 (also W staging at init)
    float* red  = h_s  + BROWS * HS_STRIDE;  // 4 x 32 x 36 partials
    float* h0_s = red  + NKW * RED_W;        // 256
    float* c_s  = h0_s + 256;                // 256

    const int tid  = threadIdx.x;
    const int blk  = blockIdx.x;
    const int bb   = blk >> 6;                // batch half 0..1
    const int jb   = blk & 63;                // j-block 0..63
    const int j0   = jb * JB;
    const int b0   = bb * BROWS;
    const int lane = tid & 31;
    const int warp = tid >> 5;
    const int kw   = warp & 3;                // K-group 0..3
    const int mh   = warp >> 2;               // m-half 0..1 (16 rows each)
    const int gid  = lane >> 2;
    const int tig  = lane & 3;
    const int kbase = kw * 128;

    // --- stage W_hh slice (32 rows x 512) into h_s temporarily, as tf32
    for (int i = tid; i < 32 * 128; i += 256) {
        int r  = i >> 7;
        int k4 = (i & 127) * 4;
        int gate = r >> 3, jl = r & 7;
        float4 v = *(const float4*)(Whh + (size_t)(gate * HID + j0 + jl) * HID + k4);
        float* d = &h_s[r * HS_STRIDE + k4];
        d[0] = tf32r(v.x); d[1] = tf32r(v.y); d[2] = tf32r(v.z); d[3] = tf32r(v.w);
    }
    // --- h0 slice (32 rows x 8 cols), c0 = h0; publish permuted tf32 h0
    for (int i = tid; i < BROWS * JB; i += 256) {
        int b = i >> 3, jl = i & 7;
        float v = h0[(b0 + b) * HID + j0 + jl];
        h0_s[i] = v;
        c_s[i]  = v;
        g_hbuf[0][(b0 + b) * HID + j0 + pjmap(jl)] = tf32r(v);
    }
    __syncthreads();

    // --- preload this warp's B fragments: breg[16][4][2], resident forever
    uint32_t breg[16][4][2];
    #pragma unroll
    for (int kk = 0; kk < 16; kk++)
        #pragma unroll
        for (int nt = 0; nt < 4; nt++) {
            const float* pb = &h_s[(nt * 8 + gid) * HS_STRIDE + kbase + kk * 8 + tig];
            breg[kk][nt][0] = __float_as_uint(pb[0]);
            breg[kk][nt][1] = __float_as_uint(pb[4]);
        }
    __syncthreads();
    // h0 published (+1 per warp; counter reaches 8)
    if (lane == 0) arrive_release(&g_cnt2[blk * 8]);

    const int rb = tid >> 3;           // 0..31 local batch row for reduce
    const int jl = tid & 7;            // 0..7 local hidden col

    const uint32_t hss = (uint32_t)__cvta_generic_to_shared(h_s);
    // poll: counter of same-half block bb*64 + 16*kw + (lane&15)
    const unsigned* pollp = &g_cnt2[(bb * 64 + kw * 16 + (lane & 15)) * 8];

    // prefetch x_proj + mask for t=0 (one gate scalar per gate per thread)
    float xq[4];
    {
        const float* xp = g_xproj + (size_t)(b0 + rb) * GDIM + j0 + jl;
        #pragma unroll
        for (int g = 0; g < 4; g++) xq[g] = xp[g * HID];
    }
    float mval = mask[b0 + rb];

    for (int t = 0; t < TSTEPS; t++) {
        const float* hin  = g_hbuf[t & 1];
        float*       hout = g_hbuf[(t + 1) & 1];

        // ---- poll 16 same-half producer counters lane-parallel
        {
            const unsigned want = 8u * (unsigned)(t + 1);
            for (;;) {
                unsigned cv = ld_acq(pollp);
                if (__all_sync(0xffffffffu, cv >= want)) break;
            }
        }

        // ---- cp.async local rows [16mh,+16) x cols [kbase,+128), 2 halves
        #pragma unroll
        for (int g = 0; g < 2; g++) {
            #pragma unroll 4
            for (int it = 0; it < 8; it++) {
                int e   = it * 32 + lane;             // 0..255
                int row = 16 * mh + (e >> 4);         // 16 rows
                int c4  = ((e & 15) << 2) + g * 64;   // 64 cols per half
                cp16(hss + (uint32_t)(row * HS_STRIDE + kbase + c4) * 4,
                     hin + (size_t)(b0 + row) * HID + kbase + c4);
            }
            asm volatile("cp.async.commit_group;" ::: "memory");
        }

        // ---- split-K MMA in two halves (LDS.64 A pairs, permuted layout)
        float acc[4][4];
        #pragma unroll
        for (int nt = 0; nt < 4; nt++)
            #pragma unroll
            for (int q = 0; q < 4; q++) acc[nt][q] = 0.0f;

#define DO_HALF(K0, PEND)                                                       \
        {                                                                       \
            asm volatile("cp.async.wait_group " #PEND ";" ::: "memory");        \
            __syncwarp();                                                       \
            _Pragma("unroll")                                                   \
            for (int kk = (K0); kk < (K0) + 8; kk++) {                          \
                int row = 16 * mh + gid;                                        \
                float2 v0 = *(const float2*)&h_s[row * HS_STRIDE                \
                                  + kbase + kk * 8 + 2 * tig];                  \
                float2 v1 = *(const float2*)&h_s[(row + 8) * HS_STRIDE          \
                                  + kbase + kk * 8 + 2 * tig];                  \
                uint32_t a[4];                                                  \
                a[0] = __float_as_uint(v0.x);                                   \
                a[1] = __float_as_uint(v1.x);                                   \
                a[2] = __float_as_uint(v0.y);                                   \
                a[3] = __float_as_uint(v1.y);                                   \
                _Pragma("unroll")                                               \
                for (int nt = 0; nt < 4; nt++)                                  \
                    mma_tf32(acc[nt], a, breg[kk][nt]);                         \
            }                                                                   \
        }
        DO_HALF(0, 1)
        DO_HALF(8, 0)
#undef DO_HALF

        // ---- store partials: red[kw][row][col], rows 16mh..16mh+16
        float* rw = red + kw * RED_W;
        #pragma unroll
        for (int nt = 0; nt < 4; nt++) {
            int row = 16 * mh + gid;
            int col = nt * 8 + 2 * tig;
            float* rp = &rw[row * RED_B + col];
            *(float2*)rp               = make_float2(acc[nt][0], acc[nt][1]);
            *(float2*)(rp + 8 * RED_B) = make_float2(acc[nt][2], acc[nt][3]);
        }
        __syncthreads();                       // bar A: partials complete

        // ---- reduce 4 partials + x_proj, LSTM cell (1 value per thread)
        float s[4];
        #pragma unroll
        for (int g = 0; g < 4; g++) s[g] = xq[g];
        #pragma unroll
        for (int w = 0; w < NKW; w++) {
            const float* rr = red + w * RED_W + rb * RED_B + jl;
            #pragma unroll
            for (int g = 0; g < 4; g++) s[g] += rr[g * 8];
        }
        float iv = sigf(s[0]);
        float fv = sigf(s[1]);
        float gv = tanhf_(s[2]);
        float ov = sigf(s[3]);
        int p = rb * 8 + jl;
        float c = fv * c_s[p] + iv * gv;
        float h = ov * tanhf_(c);
        float z = h0_s[p];                     // h0 == c0
        h = h * mval + z * (1.0f - mval);
        c = c * mval + z * (1.0f - mval);
        c_s[p] = c;
        hout[(size_t)(b0 + rb) * HID + j0 + pjmap(jl)] = tf32r(h);   // PERMUTED
        // this warp's hout values stored -> release-arrive
        __syncwarp();
        if (lane == 0) arrive_release(&g_cnt2[blk * 8]);

        // ---- shadow: out[] stores + next-step prefetch (off critical path)
        {
            int grow = b0 + rb, gcol = j0 + jl;               // UNPERMUTED
            out[(size_t)t * BATCH * HID + grow * HID + gcol] = h;
            if (t == TSTEPS - 1) {
                out[(size_t)TSTEPS * BATCH * HID               + grow * HID + gcol] = h;
                out[(size_t)TSTEPS * BATCH * HID + BATCH * HID + grow * HID + gcol] = c;
            }
        }
        if (t + 1 < TSTEPS) {
            const float* xp = g_xproj + (size_t)(t + 1) * BATCH * GDIM
                            + (size_t)(b0 + rb) * GDIM + j0 + jl;
            #pragma unroll
            for (int g = 0; g < 4; g++) xq[g] = xp[g * HID];
            mval = mask[(t + 1) * BATCH + b0 + rb];
        }
        __syncthreads();                       // bar B: red safe to overwrite
    }
}

// ============================================================================
extern "C" void kernel_launch(void* const* d_in, const int* in_sizes, int n_in,
                              void* d_out, int out_size) {
    const float* inputs = (const float*)d_in[0];   // [512,64,512]
    const float* mask   = (const float*)d_in[1];   // [512,64]
    const float* h0     = (const float*)d_in[2];   // [64,512]
    const float* W_ih   = (const float*)d_in[3];   // [2048,512]
    const float* W_hh   = (const float*)d_in[4];   // [2048,512]
    const float* b_ih   = (const float*)d_in[5];   // [2048]
    const float* b_hh   = (const float*)d_in[6];   // [2048]
    float* out = (float*)d_out;                    // out | hT | cT (fp32)

    const int smem_bytes = (BROWS * HS_STRIDE + NKW * RED_W + 512 + 32) * 4;
    cudaFuncSetAttribute(lstm_kernel, cudaFuncAttributeMaxDynamicSharedMemorySize, smem_bytes);

    dim3 xg(GDIM / 128, (TSTEPS * BATCH) / 128);   // (16, 256)
    xproj_kernel<<<xg, 256>>>(inputs, W_ih, b_ih, b_hh);

    lstm_kernel<<<LSTM_BLOCKS, 256, smem_bytes>>>(mask, h0, W_hh, out);
}

// round 12
// speedup vs baseline: 2.0084x; 1.0602x over previous
#include <cuda_runtime.h>
#include <cuda_fp16.h>
#include <cstdint>
#include <cstddef>

#define TSTEPS 512
#define BATCH  64
#define DIM    512
#define HID    512
#define GDIM   2048            // 4*HID
#define LSTM_BLOCKS 128        // (2 batch halves) x (64 j-column blocks)
#define BROWS 32               // batch rows per block
#define JB 8                   // hidden columns per recurrent block
#define HS2 528                // fp16 h_s row stride (1056B = 32 mod 128 -> conflict-free LDS.64)
#define RED_B 36               // padded partial row stride (fp32)
#define RED_W (BROWS * RED_B)  // one K-group's partial tile
#define NKW 4                  // split-K groups

// fp16 layout permutation within each 16-col group: pair p=(c>>1)&7 ->
// offset 4p (p<4) or 4(p-4)+2 (p>=4). Puts mma pairs (k,k+1),(k+8,k+9)
// adjacent so the A fragment is one LDS.64.
__host__ __device__ __forceinline__ int pjmap16(int c) {
    int p = (c >> 1) & 7, u = c & 1;
    int off = (p < 4) ? (4 * p) : (4 * (p - 4) + 2);
    return (c & ~15) | (off + u);
}

// ---------------- scratch (static device allocations; no cudaMalloc) -------
__device__ float  g_xproj[(size_t)TSTEPS * BATCH * GDIM];  // x@W_ih^T + bias
__device__ __half g_hbuf[2][BATCH * HID];                  // ping-pong hidden (fp16, PERMUTED)
__device__ unsigned g_cnt2[LSTM_BLOCKS * 8];               // per-block counters (32B sectors)

// ---------------- helpers ---------------------------------------------------
__device__ __forceinline__ float tf32r(float x) {
    uint32_t r; asm("cvt.rna.tf32.f32 %0, %1;" : "=r"(r) : "f"(x));
    return __uint_as_float(r);
}
__device__ __forceinline__ void mma_tf32(float c[4], const uint32_t a[4], const uint32_t b[2]) {
    asm volatile(
        "mma.sync.aligned.m16n8k8.row.col.f32.tf32.tf32.f32 "
        "{%0,%1,%2,%3}, {%4,%5,%6,%7}, {%8,%9}, {%0,%1,%2,%3};"
        : "+f"(c[0]), "+f"(c[1]), "+f"(c[2]), "+f"(c[3])
        : "r"(a[0]), "r"(a[1]), "r"(a[2]), "r"(a[3]), "r"(b[0]), "r"(b[1]));
}
__device__ __forceinline__ void mma_f16(float c[4], const uint32_t a[4], const uint32_t b[2]) {
    asm volatile(
        "mma.sync.aligned.m16n8k16.row.col.f32.f16.f16.f32 "
        "{%0,%1,%2,%3}, {%4,%5,%6,%7}, {%8,%9}, {%0,%1,%2,%3};"
        : "+f"(c[0]), "+f"(c[1]), "+f"(c[2]), "+f"(c[3])
        : "r"(a[0]), "r"(a[1]), "r"(a[2]), "r"(a[3]), "r"(b[0]), "r"(b[1]));
}
__device__ __forceinline__ uint32_t packh2(float lo, float hi) {
    __half2 h = __floats2half2_rn(lo, hi);
    uint32_t r; static_assert(sizeof(h) == 4, "");
    memcpy(&r, &h, 4);
    return r;
}
__device__ __forceinline__ float ex2f(float x) { float y; asm("ex2.approx.f32 %0, %1;" : "=f"(y) : "f"(x)); return y; }
__device__ __forceinline__ float rcpf(float x) { float y; asm("rcp.approx.f32 %0, %1;" : "=f"(y) : "f"(x)); return y; }
__device__ __forceinline__ float sigf(float x)  { return rcpf(1.0f + ex2f(-1.4426950408889634f * x)); }
__device__ __forceinline__ float tanhf_(float x){ return 2.0f * sigf(2.0f * x) - 1.0f; }

__device__ __forceinline__ unsigned ld_acq(const unsigned* p) {
    unsigned v; asm volatile("ld.acquire.gpu.global.u32 %0, [%1];" : "=r"(v) : "l"(p)); return v;
}
__device__ __forceinline__ void arrive_release(unsigned* p) {
    asm volatile("red.release.gpu.global.add.u32 [%0], 1;" :: "l"(p) : "memory");
}
__device__ __forceinline__ void cp16(uint32_t s, const void* g) {
    asm volatile("cp.async.cg.shared.global [%0], [%1], 16;" :: "r"(s), "l"(g));
}

// ============================================================================
// Kernel 1: x_proj = X @ W_ih^T + bias (TF32 mma, 128x128x32 tiles) +
// counter reset for the recurrence kernel. (fp32 output — gate accuracy
// is dominated by this term, keep it tf32.)
// ============================================================================
__global__ void __launch_bounds__(256) xproj_kernel(
    const float* __restrict__ X, const float* __restrict__ Wih,
    const float* __restrict__ b_ih, const float* __restrict__ b_hh)
{
    {
        int bid = blockIdx.y * gridDim.x + blockIdx.x;
        if (threadIdx.x == 0 && bid < LSTM_BLOCKS * 8) g_cnt2[bid] = 0u;
    }

    __shared__ float As[128][36];
    __shared__ float Bs[32][132];

    const int m0 = blockIdx.y * 128;
    const int n0 = blockIdx.x * 128;
    const int tid  = threadIdx.x;
    const int lane = tid & 31;
    const int warp = tid >> 5;
    const int wm = warp >> 1;
    const int wn = warp & 1;
    const int gid = lane >> 2;
    const int tig = lane & 3;

    float acc[2][8][4];
    #pragma unroll
    for (int mt = 0; mt < 2; mt++)
        #pragma unroll
        for (int nt = 0; nt < 8; nt++)
            #pragma unroll
            for (int q = 0; q < 4; q++) acc[mt][nt][q] = 0.0f;

    const int lr = tid >> 3;
    const int lc = (tid & 7) * 4;

    for (int k0 = 0; k0 < DIM; k0 += 32) {
        __syncthreads();
        #pragma unroll
        for (int p = 0; p < 4; p++) {
            int r = lr + p * 32;
            float4 v = *(const float4*)(X + (size_t)(m0 + r) * DIM + k0 + lc);
            As[r][lc+0] = tf32r(v.x); As[r][lc+1] = tf32r(v.y);
            As[r][lc+2] = tf32r(v.z); As[r][lc+3] = tf32r(v.w);
        }
        #pragma unroll
        for (int p = 0; p < 4; p++) {
            int n = lr + p * 32;
            float4 v = *(const float4*)(Wih + (size_t)(n0 + n) * DIM + k0 + lc);
            Bs[lc+0][n] = tf32r(v.x); Bs[lc+1][n] = tf32r(v.y);
            Bs[lc+2][n] = tf32r(v.z); Bs[lc+3][n] = tf32r(v.w);
        }
        __syncthreads();

        #pragma unroll
        for (int ks = 0; ks < 4; ks++) {
            const int kb = ks * 8;
            uint32_t a[2][4], b[8][2];
            #pragma unroll
            for (int mt = 0; mt < 2; mt++) {
                int row = wm * 32 + mt * 16;
                a[mt][0] = __float_as_uint(As[row + gid    ][kb + tig    ]);
                a[mt][1] = __float_as_uint(As[row + gid + 8][kb + tig    ]);
                a[mt][2] = __float_as_uint(As[row + gid    ][kb + tig + 4]);
                a[mt][3] = __float_as_uint(As[row + gid + 8][kb + tig + 4]);
            }
            #pragma unroll
            for (int nt = 0; nt < 8; nt++) {
                int col = wn * 64 + nt * 8 + gid;
                b[nt][0] = __float_as_uint(Bs[kb + tig    ][col]);
                b[nt][1] = __float_as_uint(Bs[kb + tig + 4][col]);
            }
            #pragma unroll
            for (int mt = 0; mt < 2; mt++)
                #pragma unroll
                for (int nt = 0; nt < 8; nt++)
                    mma_tf32(acc[mt][nt], a[mt], b[nt]);
        }
    }

    #pragma unroll
    for (int mt = 0; mt < 2; mt++) {
        #pragma unroll
        for (int nt = 0; nt < 8; nt++) {
            int row = m0 + wm * 32 + mt * 16 + gid;
            int col = n0 + wn * 64 + nt * 8 + 2 * tig;
            float bz0 = b_ih[col]     + b_hh[col];
            float bz1 = b_ih[col + 1] + b_hh[col + 1];
            float2 v0 = make_float2(acc[mt][nt][0] + bz0, acc[mt][nt][1] + bz1);
            float2 v1 = make_float2(acc[mt][nt][2] + bz0, acc[mt][nt][3] + bz1);
            *(float2*)(g_xproj + (size_t)row       * GDIM + col) = v0;
            *(float2*)(g_xproj + (size_t)(row + 8) * GDIM + col) = v1;
        }
    }
}

// ============================================================================
// Kernel 2: persistent recurrence, fp16 datapath.
// 128 blocks = (2 batch halves bb) x (64 j-blocks jb); block owns rows
// [32bb,+32) x gate cols of j in [8jb,+8). Warp (kw=warp&3, mh=warp>>2):
// local rows [16mh,+16), K cols [128kw,+128). h published/stored fp16 with
// 16-col interleave -> A fragments load as single LDS.64; W_hh fragments
// (fp16, breg[8][4][2]) loaded once from gmem; mma.m16n8k16.f16 with fp32
// accumulate. Per-block counters + 2-stage cp.async overlap as in R11.
// ============================================================================
__global__ void __launch_bounds__(256, 1) lstm_kernel(
    const float* __restrict__ mask, const float* __restrict__ h0,
    const float* __restrict__ Whh, float* __restrict__ out)
{
    extern __shared__ char smem_raw[];
    __half* h_s  = (__half*)smem_raw;                        // 32 x 528 fp16
    float*  red  = (float*)(smem_raw + BROWS * HS2 * 2);     // 4 x 32 x 36 fp32
    float*  h0_s = red + NKW * RED_W;                        // 256
    float*  c_s  = h0_s + 256;                               // 256

    const int tid  = threadIdx.x;
    const int blk  = blockIdx.x;
    const int bb   = blk >> 6;                // batch half 0..1
    const int jb   = blk & 63;                // j-block 0..63
    const int j0   = jb * JB;
    const int b0   = bb * BROWS;
    const int lane = tid & 31;
    const int warp = tid >> 5;
    const int kw   = warp & 3;                // K-group 0..3
    const int mh   = warp >> 2;               // m-half 0..1 (16 rows each)
    const int gid  = lane >> 2;
    const int tig  = lane & 3;
    const int kbase = kw * 128;

    // --- W_hh fragments straight from gmem (init-only), fp16-packed.
    // breg[kk][nt]: col = nt*8+gid -> W row nt*HID + j0 + gid;
    // k = kbase + kk*16 + {2tig,2tig+1} and {+8,+9}.
    uint32_t breg[8][4][2];
    #pragma unroll
    for (int kk = 0; kk < 8; kk++)
        #pragma unroll
        for (int nt = 0; nt < 4; nt++) {
            const float* wr = Whh + (size_t)(nt * HID + j0 + gid) * HID
                            + kbase + kk * 16 + 2 * tig;
            breg[kk][nt][0] = packh2(wr[0], wr[1]);
            breg[kk][nt][1] = packh2(wr[8], wr[9]);
        }

    // --- h0 slice (32 rows x 8 cols), c0 = h0; publish permuted fp16 h0
    for (int i = tid; i < BROWS * JB; i += 256) {
        int b = i >> 3, jl = i & 7;
        float v = h0[(b0 + b) * HID + j0 + jl];
        h0_s[i] = v;
        c_s[i]  = v;
        g_hbuf[0][(b0 + b) * HID + pjmap16(j0 + jl)] = __float2half_rn(v);
    }
    __syncthreads();
    // h0 published (+1 per warp; counter reaches 8)
    if (lane == 0) arrive_release(&g_cnt2[blk * 8]);

    const int rb = tid >> 3;           // 0..31 local batch row for reduce
    const int jl = tid & 7;            // 0..7 local hidden col

    const uint32_t hss = (uint32_t)__cvta_generic_to_shared(h_s);
    // poll: counter of same-half block bb*64 + 16*kw + (lane&15)
    const unsigned* pollp = &g_cnt2[(bb * 64 + kw * 16 + (lane & 15)) * 8];

    // prefetch x_proj + mask for t=0
    float xq[4];
    {
        const float* xp = g_xproj + (size_t)(b0 + rb) * GDIM + j0 + jl;
        #pragma unroll
        for (int g = 0; g < 4; g++) xq[g] = xp[g * HID];
    }
    float mval = mask[b0 + rb];

    const int jperm = pjmap16(j0 + jl);       // permuted global col for hout

    for (int t = 0; t < TSTEPS; t++) {
        const __half* hin  = g_hbuf[t & 1];
        __half*       hout = g_hbuf[(t + 1) & 1];

        // ---- poll 16 same-half producer counters lane-parallel
        {
            const unsigned want = 8u * (unsigned)(t + 1);
            for (;;) {
                unsigned cv = ld_acq(pollp);
                if (__all_sync(0xffffffffu, cv >= want)) break;
            }
        }

        // ---- cp.async local rows [16mh,+16) x fp16 cols [kbase,+128), 2 halves
        // each row-slice is 256B; half g covers bytes [g*128, +128)
        #pragma unroll
        for (int g = 0; g < 2; g++) {
            #pragma unroll 4
            for (int it = 0; it < 4; it++) {
                int e   = it * 32 + lane;             // 0..127
                int row = 16 * mh + (e >> 3);         // 16 rows, 8 chunks each
                int ce  = g * 64 + (e & 7) * 8;       // fp16 element offset in slice
                cp16(hss + (uint32_t)(row * HS2 + kbase + ce) * 2,
                     hin + (size_t)(b0 + row) * HID + kbase + ce);
            }
            asm volatile("cp.async.commit_group;" ::: "memory");
        }

        // ---- fp16 MMA in two halves (A = one LDS.64 per row-pair)
        float acc[4][4];
        #pragma unroll
        for (int nt = 0; nt < 4; nt++)
            #pragma unroll
            for (int q = 0; q < 4; q++) acc[nt][q] = 0.0f;

#define DO_HALF(K0, PEND)                                                       \
        {                                                                       \
            asm volatile("cp.async.wait_group " #PEND ";" ::: "memory");        \
            __syncwarp();                                                       \
            _Pragma("unroll")                                                   \
            for (int kk = (K0); kk < (K0) + 4; kk++) {                          \
                int row = 16 * mh + gid;                                        \
                uint2 v0 = *(const uint2*)&h_s[row * HS2                        \
                                  + kbase + kk * 16 + 4 * tig];                 \
                uint2 v1 = *(const uint2*)&h_s[(row + 8) * HS2                  \
                                  + kbase + kk * 16 + 4 * tig];                 \
                uint32_t a[4];                                                  \
                a[0] = v0.x;  /* rows 0-7,  k..k+1  */                          \
                a[1] = v1.x;  /* rows 8-15, k..k+1  */                          \
                a[2] = v0.y;  /* rows 0-7,  k+8..k+9 */                         \
                a[3] = v1.y;  /* rows 8-15, k+8..k+9 */                         \
                _Pragma("unroll")                                               \
                for (int nt = 0; nt < 4; nt++)                                  \
                    mma_f16(acc[nt], a, breg[kk][nt]);                          \
            }                                                                   \
        }
        DO_HALF(0, 1)
        DO_HALF(4, 0)
#undef DO_HALF

        // ---- store partials: red[kw][row][col], rows 16mh..16mh+16
        float* rw = red + kw * RED_W;
        #pragma unroll
        for (int nt = 0; nt < 4; nt++) {
            int row = 16 * mh + gid;
            int col = nt * 8 + 2 * tig;
            float* rp = &rw[row * RED_B + col];
            *(float2*)rp               = make_float2(acc[nt][0], acc[nt][1]);
            *(float2*)(rp + 8 * RED_B) = make_float2(acc[nt][2], acc[nt][3]);
        }
        __syncthreads();                       // bar A: partials complete

        // ---- reduce 4 partials + x_proj, LSTM cell (1 value per thread)
        float s[4];
        #pragma unroll
        for (int g = 0; g < 4; g++) s[g] = xq[g];
        #pragma unroll
        for (int w = 0; w < NKW; w++) {
            const float* rr = red + w * RED_W + rb * RED_B + jl;
            #pragma unroll
            for (int g = 0; g < 4; g++) s[g] += rr[g * 8];
        }
        float iv = sigf(s[0]);
        float fv = sigf(s[1]);
        float gv = tanhf_(s[2]);
        float ov = sigf(s[3]);
        int p = rb * 8 + jl;
        float c = fv * c_s[p] + iv * gv;
        float h = ov * tanhf_(c);
        float z = h0_s[p];                     // h0 == c0
        h = h * mval + z * (1.0f - mval);
        c = c * mval + z * (1.0f - mval);
        c_s[p] = c;
        hout[(size_t)(b0 + rb) * HID + jperm] = __float2half_rn(h);
        // this warp's hout values stored -> release-arrive
        __syncwarp();
        if (lane == 0) arrive_release(&g_cnt2[blk * 8]);

        // ---- shadow: out[] stores + next-step prefetch (off critical path)
        {
            int grow = b0 + rb, gcol = j0 + jl;
            out[(size_t)t * BATCH * HID + grow * HID + gcol] = h;
            if (t == TSTEPS - 1) {
                out[(size_t)TSTEPS * BATCH * HID               + grow * HID + gcol] = h;
                out[(size_t)TSTEPS * BATCH * HID + BATCH * HID + grow * HID + gcol] = c;
            }
        }
        if (t + 1 < TSTEPS) {
            const float* xp = g_xproj + (size_t)(t + 1) * BATCH * GDIM
                            + (size_t)(b0 + rb) * GDIM + j0 + jl;
            #pragma unroll
            for (int g = 0; g < 4; g++) xq[g] = xp[g * HID];
            mval = mask[(t + 1) * BATCH + b0 + rb];
        }
        __syncthreads();                       // bar B: red safe to overwrite
    }
}

// ============================================================================
extern "C" void kernel_launch(void* const* d_in, const int* in_sizes, int n_in,
                              void* d_out, int out_size) {
    const float* inputs = (const float*)d_in[0];   // [512,64,512]
    const float* mask   = (const float*)d_in[1];   // [512,64]
    const float* h0     = (const float*)d_in[2];   // [64,512]
    const float* W_ih   = (const float*)d_in[3];   // [2048,512]
    const float* W_hh   = (const float*)d_in[4];   // [2048,512]
    const float* b_ih   = (const float*)d_in[5];   // [2048]
    const float* b_hh   = (const float*)d_in[6];   // [2048]
    float* out = (float*)d_out;                    // out | hT | cT (fp32)

    const int smem_bytes = BROWS * HS2 * 2 + (NKW * RED_W + 512 + 32) * 4;
    cudaFuncSetAttribute(lstm_kernel, cudaFuncAttributeMaxDynamicSharedMemorySize, smem_bytes);

    dim3 xg(GDIM / 128, (TSTEPS * BATCH) / 128);   // (16, 256)
    xproj_kernel<<<xg, 256>>>(inputs, W_ih, b_ih, b_hh);

    lstm_kernel<<<LSTM_BLOCKS, 256, smem_bytes>>>(mask, h0, W_hh, out);
}

// round 13
// speedup vs baseline: 2.0551x; 1.0232x over previous
#include <cuda_runtime.h>
#include <cuda_fp16.h>
#include <cstdint>
#include <cstddef>

#define TSTEPS 512
#define BATCH  64
#define DIM    512
#define HID    512
#define GDIM   2048            // 4*HID
#define LSTM_BLOCKS 256        // (4 batch quarters) x (64 j-column blocks)
#define BROWS 16               // batch rows per block
#define JB 8                   // hidden columns per recurrent block
#define HS2 528                // fp16 h_s row stride (1056B = 32 mod 128 -> conflict-free LDS.64)
#define RED_B 36               // padded partial row stride (fp32)
#define RED_W (BROWS * RED_B)  // one K-group's partial tile
#define NKW 4                  // split-K groups (= warps per block)

// fp16 layout permutation within each 16-col group: pair p=(c>>1)&7 ->
// offset 4p (p<4) or 4(p-4)+2 (p>=4). Puts mma pairs (k,k+1),(k+8,k+9)
// adjacent so the A fragment is one LDS.64.
__host__ __device__ __forceinline__ int pjmap16(int c) {
    int p = (c >> 1) & 7, u = c & 1;
    int off = (p < 4) ? (4 * p) : (4 * (p - 4) + 2);
    return (c & ~15) | (off + u);
}

// ---------------- scratch (static device allocations; no cudaMalloc) -------
__device__ float  g_xproj[(size_t)TSTEPS * BATCH * GDIM];  // x@W_ih^T + bias
__device__ __half g_hbuf[2][BATCH * HID];                  // ping-pong hidden (fp16, PERMUTED)
__device__ unsigned g_cnt2[LSTM_BLOCKS * 8];               // per-block counters (32B sectors)

// ---------------- helpers ---------------------------------------------------
__device__ __forceinline__ float tf32r(float x) {
    uint32_t r; asm("cvt.rna.tf32.f32 %0, %1;" : "=r"(r) : "f"(x));
    return __uint_as_float(r);
}
__device__ __forceinline__ void mma_tf32(float c[4], const uint32_t a[4], const uint32_t b[2]) {
    asm volatile(
        "mma.sync.aligned.m16n8k8.row.col.f32.tf32.tf32.f32 "
        "{%0,%1,%2,%3}, {%4,%5,%6,%7}, {%8,%9}, {%0,%1,%2,%3};"
        : "+f"(c[0]), "+f"(c[1]), "+f"(c[2]), "+f"(c[3])
        : "r"(a[0]), "r"(a[1]), "r"(a[2]), "r"(a[3]), "r"(b[0]), "r"(b[1]));
}
__device__ __forceinline__ void mma_f16(float c[4], const uint32_t a[4], const uint32_t b[2]) {
    asm volatile(
        "mma.sync.aligned.m16n8k16.row.col.f32.f16.f16.f32 "
        "{%0,%1,%2,%3}, {%4,%5,%6,%7}, {%8,%9}, {%0,%1,%2,%3};"
        : "+f"(c[0]), "+f"(c[1]), "+f"(c[2]), "+f"(c[3])
        : "r"(a[0]), "r"(a[1]), "r"(a[2]), "r"(a[3]), "r"(b[0]), "r"(b[1]));
}
__device__ __forceinline__ uint32_t packh2(float lo, float hi) {
    __half2 h = __floats2half2_rn(lo, hi);
    uint32_t r; memcpy(&r, &h, 4);
    return r;
}
__device__ __forceinline__ float ex2f(float x) { float y; asm("ex2.approx.f32 %0, %1;" : "=f"(y) : "f"(x)); return y; }
__device__ __forceinline__ float rcpf(float x) { float y; asm("rcp.approx.f32 %0, %1;" : "=f"(y) : "f"(x)); return y; }
__device__ __forceinline__ float sigf(float x)  { return rcpf(1.0f + ex2f(-1.4426950408889634f * x)); }
__device__ __forceinline__ float tanhf_(float x){ return 2.0f * sigf(2.0f * x) - 1.0f; }

__device__ __forceinline__ unsigned ld_acq(const unsigned* p) {
    unsigned v; asm volatile("ld.acquire.gpu.global.u32 %0, [%1];" : "=r"(v) : "l"(p)); return v;
}
__device__ __forceinline__ void arrive_release(unsigned* p) {
    asm volatile("red.release.gpu.global.add.u32 [%0], 1;" :: "l"(p) : "memory");
}
__device__ __forceinline__ void cp16(uint32_t s, const void* g) {
    asm volatile("cp.async.cg.shared.global [%0], [%1], 16;" :: "r"(s), "l"(g));
}

// ============================================================================
// Kernel 1: x_proj = X @ W_ih^T + bias (TF32 mma, 128x128x32 tiles) +
// counter reset for the recurrence kernel.
// ============================================================================
__global__ void __launch_bounds__(256) xproj_kernel(
    const float* __restrict__ X, const float* __restrict__ Wih,
    const float* __restrict__ b_ih, const float* __restrict__ b_hh)
{
    {
        int bid = blockIdx.y * gridDim.x + blockIdx.x;
        if (threadIdx.x == 0 && bid < LSTM_BLOCKS * 8) g_cnt2[bid] = 0u;
    }

    __shared__ float As[128][36];
    __shared__ float Bs[32][132];

    const int m0 = blockIdx.y * 128;
    const int n0 = blockIdx.x * 128;
    const int tid  = threadIdx.x;
    const int lane = tid & 31;
    const int warp = tid >> 5;
    const int wm = warp >> 1;
    const int wn = warp & 1;
    const int gid = lane >> 2;
    const int tig = lane & 3;

    float acc[2][8][4];
    #pragma unroll
    for (int mt = 0; mt < 2; mt++)
        #pragma unroll
        for (int nt = 0; nt < 8; nt++)
            #pragma unroll
            for (int q = 0; q < 4; q++) acc[mt][nt][q] = 0.0f;

    const int lr = tid >> 3;
    const int lc = (tid & 7) * 4;

    for (int k0 = 0; k0 < DIM; k0 += 32) {
        __syncthreads();
        #pragma unroll
        for (int p = 0; p < 4; p++) {
            int r = lr + p * 32;
            float4 v = *(const float4*)(X + (size_t)(m0 + r) * DIM + k0 + lc);
            As[r][lc+0] = tf32r(v.x); As[r][lc+1] = tf32r(v.y);
            As[r][lc+2] = tf32r(v.z); As[r][lc+3] = tf32r(v.w);
        }
        #pragma unroll
        for (int p = 0; p < 4; p++) {
            int n = lr + p * 32;
            float4 v = *(const float4*)(Wih + (size_t)(n0 + n) * DIM + k0 + lc);
            Bs[lc+0][n] = tf32r(v.x); Bs[lc+1][n] = tf32r(v.y);
            Bs[lc+2][n] = tf32r(v.z); Bs[lc+3][n] = tf32r(v.w);
        }
        __syncthreads();

        #pragma unroll
        for (int ks = 0; ks < 4; ks++) {
            const int kb = ks * 8;
            uint32_t a[2][4], b[8][2];
            #pragma unroll
            for (int mt = 0; mt < 2; mt++) {
                int row = wm * 32 + mt * 16;
                a[mt][0] = __float_as_uint(As[row + gid    ][kb + tig    ]);
                a[mt][1] = __float_as_uint(As[row + gid + 8][kb + tig    ]);
                a[mt][2] = __float_as_uint(As[row + gid    ][kb + tig + 4]);
                a[mt][3] = __float_as_uint(As[row + gid + 8][kb + tig + 4]);
            }
            #pragma unroll
            for (int nt = 0; nt < 8; nt++) {
                int col = wn * 64 + nt * 8 + gid;
                b[nt][0] = __float_as_uint(Bs[kb + tig    ][col]);
                b[nt][1] = __float_as_uint(Bs[kb + tig + 4][col]);
            }
            #pragma unroll
            for (int mt = 0; mt < 2; mt++)
                #pragma unroll
                for (int nt = 0; nt < 8; nt++)
                    mma_tf32(acc[mt][nt], a[mt], b[nt]);
        }
    }

    #pragma unroll
    for (int mt = 0; mt < 2; mt++) {
        #pragma unroll
        for (int nt = 0; nt < 8; nt++) {
            int row = m0 + wm * 32 + mt * 16 + gid;
            int col = n0 + wn * 64 + nt * 8 + 2 * tig;
            float bz0 = b_ih[col]     + b_hh[col];
            float bz1 = b_ih[col + 1] + b_hh[col + 1];
            float2 v0 = make_float2(acc[mt][nt][0] + bz0, acc[mt][nt][1] + bz1);
            float2 v1 = make_float2(acc[mt][nt][2] + bz0, acc[mt][nt][3] + bz1);
            *(float2*)(g_xproj + (size_t)row       * GDIM + col) = v0;
            *(float2*)(g_xproj + (size_t)(row + 8) * GDIM + col) = v1;
        }
    }
}

// ============================================================================
// Kernel 2: persistent recurrence, fp16, FOUR independent batch-quarter
// chains interleaved on the SMs for latency hiding.
// 256 blocks = (4 quarters bb) x (64 j-blocks jb); 128 threads (4 warps).
// Block owns rows [16bb,+16) x gate cols of j in [8jb,+8). Warp kw: all 16
// rows, K cols [128kw,+128): 32 mma.m16n8k16. Counters +4/step; consumer
// warp kw polls the 16 same-quarter producers bb*64+16kw..+15. With ~2
// blocks/SM from different quarters, one chain's poll latency is hidden
// behind the other chain's compute.
// ============================================================================
__global__ void __launch_bounds__(128, 2) lstm_kernel(
    const float* __restrict__ mask, const float* __restrict__ h0,
    const float* __restrict__ Whh, float* __restrict__ out)
{
    extern __shared__ char smem_raw[];
    __half* h_s  = (__half*)smem_raw;                        // 16 x 528 fp16
    float*  red  = (float*)(smem_raw + BROWS * HS2 * 2);     // 4 x 16 x 36 fp32
    float*  h0_s = red + NKW * RED_W;                        // 128
    float*  c_s  = h0_s + 128;                               // 128

    const int tid  = threadIdx.x;
    const int blk  = blockIdx.x;
    const int bb   = blk >> 6;                // batch quarter 0..3
    const int jb   = blk & 63;                // j-block 0..63
    const int j0   = jb * JB;
    const int b0   = bb * BROWS;
    const int lane = tid & 31;
    const int kw   = tid >> 5;                // warp = K-group 0..3
    const int gid  = lane >> 2;
    const int tig  = lane & 3;
    const int kbase = kw * 128;

    // --- W_hh fragments straight from gmem (init-only), fp16-packed.
    uint32_t breg[8][4][2];
    #pragma unroll
    for (int kk = 0; kk < 8; kk++)
        #pragma unroll
        for (int nt = 0; nt < 4; nt++) {
            const float* wr = Whh + (size_t)(nt * HID + j0 + gid) * HID
                            + kbase + kk * 16 + 2 * tig;
            breg[kk][nt][0] = packh2(wr[0], wr[1]);
            breg[kk][nt][1] = packh2(wr[8], wr[9]);
        }

    // --- h0 slice (16 rows x 8 cols), c0 = h0; publish permuted fp16 h0
    for (int i = tid; i < BROWS * JB; i += 128) {
        int b = i >> 3, jl = i & 7;
        float v = h0[(b0 + b) * HID + j0 + jl];
        h0_s[i] = v;
        c_s[i]  = v;
        g_hbuf[0][(b0 + b) * HID + pjmap16(j0 + jl)] = __float2half_rn(v);
    }
    __syncthreads();
    // h0 published (+1 per warp; counter reaches 4)
    if (lane == 0) arrive_release(&g_cnt2[blk * 8]);

    const int rb = tid >> 3;           // 0..15 local batch row for reduce
    const int jl = tid & 7;            // 0..7 local hidden col

    const uint32_t hss = (uint32_t)__cvta_generic_to_shared(h_s);
    // poll: counter of same-quarter block bb*64 + 16*kw + (lane&15)
    const unsigned* pollp = &g_cnt2[(bb * 64 + kw * 16 + (lane & 15)) * 8];

    // prefetch x_proj + mask for t=0
    float xq[4];
    {
        const float* xp = g_xproj + (size_t)(b0 + rb) * GDIM + j0 + jl;
        #pragma unroll
        for (int g = 0; g < 4; g++) xq[g] = xp[g * HID];
    }
    float mval = mask[b0 + rb];

    const int jperm = pjmap16(j0 + jl);       // permuted global col for hout

    for (int t = 0; t < TSTEPS; t++) {
        const __half* hin  = g_hbuf[t & 1];
        __half*       hout = g_hbuf[(t + 1) & 1];

        // ---- poll 16 same-quarter producer counters lane-parallel
        {
            const unsigned want = 4u * (unsigned)(t + 1);
            for (;;) {
                unsigned cv = ld_acq(pollp);
                if (__all_sync(0xffffffffu, cv >= want)) break;
            }
        }

        // ---- cp.async local rows [0,16) x fp16 cols [kbase,+128), 2 halves
        #pragma unroll
        for (int g = 0; g < 2; g++) {
            #pragma unroll 4
            for (int it = 0; it < 4; it++) {
                int e   = it * 32 + lane;             // 0..127
                int row = e >> 3;                     // 16 rows, 8 chunks each
                int ce  = g * 64 + (e & 7) * 8;       // fp16 element offset
                cp16(hss + (uint32_t)(row * HS2 + kbase + ce) * 2,
                     hin + (size_t)(b0 + row) * HID + kbase + ce);
            }
            asm volatile("cp.async.commit_group;" ::: "memory");
        }

        // ---- fp16 MMA in two halves (A = one LDS.64 per row-pair)
        float acc[4][4];
        #pragma unroll
        for (int nt = 0; nt < 4; nt++)
            #pragma unroll
            for (int q = 0; q < 4; q++) acc[nt][q] = 0.0f;

#define DO_HALF(K0, PEND)                                                       \
        {                                                                       \
            asm volatile("cp.async.wait_group " #PEND ";" ::: "memory");        \
            __syncwarp();                                                       \
            _Pragma("unroll")                                                   \
            for (int kk = (K0); kk < (K0) + 4; kk++) {                          \
                uint2 v0 = *(const uint2*)&h_s[gid * HS2                        \
                                  + kbase + kk * 16 + 4 * tig];                 \
                uint2 v1 = *(const uint2*)&h_s[(gid + 8) * HS2                  \
                                  + kbase + kk * 16 + 4 * tig];                 \
                uint32_t a[4];                                                  \
                a[0] = v0.x;                                                    \
                a[1] = v1.x;                                                    \
                a[2] = v0.y;                                                    \
                a[3] = v1.y;                                                    \
                _Pragma("unroll")                                               \
                for (int nt = 0; nt < 4; nt++)                                  \
                    mma_f16(acc[nt], a, breg[kk][nt]);                          \
            }                                                                   \
        }
        DO_HALF(0, 1)
        DO_HALF(4, 0)
#undef DO_HALF

        // ---- store partials: red[kw][row][col], 16 rows
        float* rw = red + kw * RED_W;
        #pragma unroll
        for (int nt = 0; nt < 4; nt++) {
            int col = nt * 8 + 2 * tig;
            float* rp = &rw[gid * RED_B + col];
            *(float2*)rp               = make_float2(acc[nt][0], acc[nt][1]);
            *(float2*)(rp + 8 * RED_B) = make_float2(acc[nt][2], acc[nt][3]);
        }
        __syncthreads();                       // bar A: partials complete

        // ---- reduce 4 partials + x_proj, LSTM cell (1 value per thread)
        float s[4];
        #pragma unroll
        for (int g = 0; g < 4; g++) s[g] = xq[g];
        #pragma unroll
        for (int w = 0; w < NKW; w++) {
            const float* rr = red + w * RED_W + rb * RED_B + jl;
            #pragma unroll
            for (int g = 0; g < 4; g++) s[g] += rr[g * 8];
        }
        float iv = sigf(s[0]);
        float fv = sigf(s[1]);
        float gv = tanhf_(s[2]);
        float ov = sigf(s[3]);
        int p = rb * 8 + jl;
        float c = fv * c_s[p] + iv * gv;
        float h = ov * tanhf_(c);
        float z = h0_s[p];                     // h0 == c0
        h = h * mval + z * (1.0f - mval);
        c = c * mval + z * (1.0f - mval);
        c_s[p] = c;
        hout[(size_t)(b0 + rb) * HID + jperm] = __float2half_rn(h);
        // this warp's hout values stored -> release-arrive
        __syncwarp();
        if (lane == 0) arrive_release(&g_cnt2[blk * 8]);

        // ---- shadow: out[] stores + next-step prefetch (off critical path)
        {
            int grow = b0 + rb, gcol = j0 + jl;
            out[(size_t)t * BATCH * HID + grow * HID + gcol] = h;
            if (t == TSTEPS - 1) {
                out[(size_t)TSTEPS * BATCH * HID               + grow * HID + gcol] = h;
                out[(size_t)TSTEPS * BATCH * HID + BATCH * HID + grow * HID + gcol] = c;
            }
        }
        if (t + 1 < TSTEPS) {
            const float* xp = g_xproj + (size_t)(t + 1) * BATCH * GDIM
                            + (size_t)(b0 + rb) * GDIM + j0 + jl;
            #pragma unroll
            for (int g = 0; g < 4; g++) xq[g] = xp[g * HID];
            mval = mask[(t + 1) * BATCH + b0 + rb];
        }
        __syncthreads();                       // bar B: red safe to overwrite
    }
}

// ============================================================================
extern "C" void kernel_launch(void* const* d_in, const int* in_sizes, int n_in,
                              void* d_out, int out_size) {
    const float* inputs = (const float*)d_in[0];   // [512,64,512]
    const float* mask   = (const float*)d_in[1];   // [512,64]
    const float* h0     = (const float*)d_in[2];   // [64,512]
    const float* W_ih   = (const float*)d_in[3];   // [2048,512]
    const float* W_hh   = (const float*)d_in[4];   // [2048,512]
    const float* b_ih   = (const float*)d_in[5];   // [2048]
    const float* b_hh   = (const float*)d_in[6];   // [2048]
    float* out = (float*)d_out;                    // out | hT | cT (fp32)

    const int smem_bytes = BROWS * HS2 * 2 + (NKW * RED_W + 256 + 32) * 4;
    cudaFuncSetAttribute(lstm_kernel, cudaFuncAttributeMaxDynamicSharedMemorySize, smem_bytes);

    dim3 xg(GDIM / 128, (TSTEPS * BATCH) / 128);   // (16, 256)
    xproj_kernel<<<xg, 256>>>(inputs, W_ih, b_ih, b_hh);

    lstm_kernel<<<LSTM_BLOCKS, 128, smem_bytes>>>(mask, h0, W_hh, out);
}

// round 14
// speedup vs baseline: 2.3957x; 1.1657x over previous
#include <cuda_runtime.h>
#include <cuda_fp16.h>
#include <cstdint>
#include <cstddef>

#define TSTEPS 512
#define BATCH  64
#define DIM    512
#define HID    512
#define GDIM   2048            // 4*HID
#define LSTM_BLOCKS 256        // (4 batch quarters) x (64 j-column blocks)
#define BROWS 16               // batch rows per block
#define JB 8                   // hidden columns per recurrent block
#define HS2 528                // fp16 h_s row stride (conflict-free LDS.64)
#define RED_B 36               // padded partial row stride (fp32)
#define RED_W (BROWS * RED_B)  // one K-group's partial tile
#define NKW 4                  // split-K groups (= warps per block)
#define XKT 64                 // xproj K-tile (fp16)
#define XS 72                  // xproj SMEM row stride in halves (64+8)

// fp16 layout permutation within each 16-col group: puts mma pairs
// (k,k+1),(k+8,k+9) adjacent so the A fragment is one LDS.64.
__host__ __device__ __forceinline__ int pjmap16(int c) {
    int p = (c >> 1) & 7, u = c & 1;
    int off = (p < 4) ? (4 * p) : (4 * (p - 4) + 2);
    return (c & ~15) | (off + u);
}

// ---------------- scratch (static device allocations; no cudaMalloc) -------
__device__ float  g_xproj[(size_t)TSTEPS * BATCH * GDIM];  // x@W_ih^T + bias
__device__ __half g_hbuf[2][BATCH * HID];                  // ping-pong hidden (fp16, PERMUTED)
__device__ unsigned g_cnt2[LSTM_BLOCKS * 8];               // per-block counters (32B sectors)

// ---------------- helpers ---------------------------------------------------
__device__ __forceinline__ void mma_f16(float c[4], const uint32_t a[4], const uint32_t b[2]) {
    asm volatile(
        "mma.sync.aligned.m16n8k16.row.col.f32.f16.f16.f32 "
        "{%0,%1,%2,%3}, {%4,%5,%6,%7}, {%8,%9}, {%0,%1,%2,%3};"
        : "+f"(c[0]), "+f"(c[1]), "+f"(c[2]), "+f"(c[3])
        : "r"(a[0]), "r"(a[1]), "r"(a[2]), "r"(a[3]), "r"(b[0]), "r"(b[1]));
}
__device__ __forceinline__ uint32_t packh2(float lo, float hi) {
    __half2 h = __floats2half2_rn(lo, hi);
    uint32_t r; memcpy(&r, &h, 4);
    return r;
}
__device__ __forceinline__ float ex2f(float x) { float y; asm("ex2.approx.f32 %0, %1;" : "=f"(y) : "f"(x)); return y; }
__device__ __forceinline__ float rcpf(float x) { float y; asm("rcp.approx.f32 %0, %1;" : "=f"(y) : "f"(x)); return y; }
__device__ __forceinline__ float sigf(float x)  { return rcpf(1.0f + ex2f(-1.4426950408889634f * x)); }
__device__ __forceinline__ float tanhf_(float x){ return 2.0f * sigf(2.0f * x) - 1.0f; }

__device__ __forceinline__ unsigned ld_acq(const unsigned* p) {
    unsigned v; asm volatile("ld.acquire.gpu.global.u32 %0, [%1];" : "=r"(v) : "l"(p)); return v;
}
__device__ __forceinline__ void arrive_release(unsigned* p) {
    asm volatile("red.release.gpu.global.add.u32 [%0], 1;" :: "l"(p) : "memory");
}
__device__ __forceinline__ void cp16(uint32_t s, const void* g) {
    asm volatile("cp.async.cg.shared.global [%0], [%1], 16;" :: "r"(s), "l"(g));
}

// ============================================================================
// Kernel 1: x_proj = X @ W_ih^T + bias — fp16 mma.m16n8k16, fp32 accumulate.
// M = 32768, N = 2048, K = 512, 128x128 tiles, K-tile 64 (8 iterations).
// Inter-block overlap (28 blocks/SM queued, 2 resident) hides the per-tile
// load/sync latency. Also resets the lstm counters.
// ============================================================================
__global__ void __launch_bounds__(256) xproj_kernel(
    const float* __restrict__ X, const float* __restrict__ Wih,
    const float* __restrict__ b_ih, const float* __restrict__ b_hh)
{
    {
        int bid = blockIdx.y * gridDim.x + blockIdx.x;
        if (threadIdx.x == 0 && bid < LSTM_BLOCKS * 8) g_cnt2[bid] = 0u;
    }

    __shared__ __half As[128][XS];
    __shared__ __half Bs[128][XS];

    const int m0 = blockIdx.y * 128;
    const int n0 = blockIdx.x * 128;
    const int tid  = threadIdx.x;
    const int lane = tid & 31;
    const int warp = tid >> 5;
    const int wm = warp >> 1;       // 0..3 : 32 output rows each
    const int wn = warp & 1;        // 0..1 : 64 output cols each
    const int gid = lane >> 2;      // 0..7
    const int tig = lane & 3;       // 0..3

    float acc[2][8][4];
    #pragma unroll
    for (int mt = 0; mt < 2; mt++)
        #pragma unroll
        for (int nt = 0; nt < 8; nt++)
            #pragma unroll
            for (int q = 0; q < 4; q++) acc[mt][nt][q] = 0.0f;

    for (int kt = 0; kt < DIM / XKT; kt++) {
        __syncthreads();
        // load + convert tile: 128 rows x 64 cols fp32 -> fp16 (A and B)
        #pragma unroll
        for (int it = 0; it < 8; it++) {
            int e  = it * 256 + tid;        // 0..2047 float4 slots
            int r  = e >> 4;                // 0..127
            int c4 = (e & 15) * 4;          // 0..60
            float4 va = *(const float4*)(X + (size_t)(m0 + r) * DIM + kt * XKT + c4);
            *(uint32_t*)&As[r][c4]     = packh2(va.x, va.y);
            *(uint32_t*)&As[r][c4 + 2] = packh2(va.z, va.w);
            float4 vb = *(const float4*)(Wih + (size_t)(n0 + r) * DIM + kt * XKT + c4);
            *(uint32_t*)&Bs[r][c4]     = packh2(vb.x, vb.y);
            *(uint32_t*)&Bs[r][c4 + 2] = packh2(vb.z, vb.w);
        }
        __syncthreads();

        #pragma unroll
        for (int ks = 0; ks < 4; ks++) {
            const int kb = ks * 16;
            uint32_t a[2][4], b[8][2];
            #pragma unroll
            for (int mt = 0; mt < 2; mt++) {
                int row = wm * 32 + mt * 16 + gid;
                a[mt][0] = *(const uint32_t*)&As[row    ][kb + 2 * tig];
                a[mt][1] = *(const uint32_t*)&As[row + 8][kb + 2 * tig];
                a[mt][2] = *(const uint32_t*)&As[row    ][kb + 2 * tig + 8];
                a[mt][3] = *(const uint32_t*)&As[row + 8][kb + 2 * tig + 8];
            }
            #pragma unroll
            for (int nt = 0; nt < 8; nt++) {
                int col = wn * 64 + nt * 8 + gid;
                b[nt][0] = *(const uint32_t*)&Bs[col][kb + 2 * tig];
                b[nt][1] = *(const uint32_t*)&Bs[col][kb + 2 * tig + 8];
            }
            #pragma unroll
            for (int mt = 0; mt < 2; mt++)
                #pragma unroll
                for (int nt = 0; nt < 8; nt++)
                    mma_f16(acc[mt][nt], a[mt], b[nt]);
        }
    }

    // epilogue: add bias, write fp32
    #pragma unroll
    for (int mt = 0; mt < 2; mt++) {
        #pragma unroll
        for (int nt = 0; nt < 8; nt++) {
            int row = m0 + wm * 32 + mt * 16 + gid;
            int col = n0 + wn * 64 + nt * 8 + 2 * tig;
            float bz0 = b_ih[col]     + b_hh[col];
            float bz1 = b_ih[col + 1] + b_hh[col + 1];
            float2 v0 = make_float2(acc[mt][nt][0] + bz0, acc[mt][nt][1] + bz1);
            float2 v1 = make_float2(acc[mt][nt][2] + bz0, acc[mt][nt][3] + bz1);
            *(float2*)(g_xproj + (size_t)row       * GDIM + col) = v0;
            *(float2*)(g_xproj + (size_t)(row + 8) * GDIM + col) = v1;
        }
    }
}

// ============================================================================
// Kernel 2: persistent recurrence (UNCHANGED from R13 best).
// 256 blocks = (4 quarters) x (64 j-blocks); 128 threads (4 warps = split-K).
// fp16 permuted h, register-resident W_hh, per-block counters, 2-stage
// cp.async/MMA overlap.
// ============================================================================
__global__ void __launch_bounds__(128, 2) lstm_kernel(
    const float* __restrict__ mask, const float* __restrict__ h0,
    const float* __restrict__ Whh, float* __restrict__ out)
{
    extern __shared__ char smem_raw[];
    __half* h_s  = (__half*)smem_raw;                        // 16 x 528 fp16
    float*  red  = (float*)(smem_raw + BROWS * HS2 * 2);     // 4 x 16 x 36 fp32
    float*  h0_s = red + NKW * RED_W;                        // 128
    float*  c_s  = h0_s + 128;                               // 128

    const int tid  = threadIdx.x;
    const int blk  = blockIdx.x;
    const int bb   = blk >> 6;                // batch quarter 0..3
    const int jb   = blk & 63;                // j-block 0..63
    const int j0   = jb * JB;
    const int b0   = bb * BROWS;
    const int lane = tid & 31;
    const int kw   = tid >> 5;                // warp = K-group 0..3
    const int gid  = lane >> 2;
    const int tig  = lane & 3;
    const int kbase = kw * 128;

    // --- W_hh fragments straight from gmem (init-only), fp16-packed.
    uint32_t breg[8][4][2];
    #pragma unroll
    for (int kk = 0; kk < 8; kk++)
        #pragma unroll
        for (int nt = 0; nt < 4; nt++) {
            const float* wr = Whh + (size_t)(nt * HID + j0 + gid) * HID
                            + kbase + kk * 16 + 2 * tig;
            breg[kk][nt][0] = packh2(wr[0], wr[1]);
            breg[kk][nt][1] = packh2(wr[8], wr[9]);
        }

    // --- h0 slice (16 rows x 8 cols), c0 = h0; publish permuted fp16 h0
    for (int i = tid; i < BROWS * JB; i += 128) {
        int b = i >> 3, jl = i & 7;
        float v = h0[(b0 + b) * HID + j0 + jl];
        h0_s[i] = v;
        c_s[i]  = v;
        g_hbuf[0][(b0 + b) * HID + pjmap16(j0 + jl)] = __float2half_rn(v);
    }
    __syncthreads();
    if (lane == 0) arrive_release(&g_cnt2[blk * 8]);

    const int rb = tid >> 3;           // 0..15 local batch row for reduce
    const int jl = tid & 7;            // 0..7 local hidden col

    const uint32_t hss = (uint32_t)__cvta_generic_to_shared(h_s);
    const unsigned* pollp = &g_cnt2[(bb * 64 + kw * 16 + (lane & 15)) * 8];

    float xq[4];
    {
        const float* xp = g_xproj + (size_t)(b0 + rb) * GDIM + j0 + jl;
        #pragma unroll
        for (int g = 0; g < 4; g++) xq[g] = xp[g * HID];
    }
    float mval = mask[b0 + rb];

    const int jperm = pjmap16(j0 + jl);

    for (int t = 0; t < TSTEPS; t++) {
        const __half* hin  = g_hbuf[t & 1];
        __half*       hout = g_hbuf[(t + 1) & 1];

        {
            const unsigned want = 4u * (unsigned)(t + 1);
            for (;;) {
                unsigned cv = ld_acq(pollp);
                if (__all_sync(0xffffffffu, cv >= want)) break;
            }
        }

        #pragma unroll
        for (int g = 0; g < 2; g++) {
            #pragma unroll 4
            for (int it = 0; it < 4; it++) {
                int e   = it * 32 + lane;
                int row = e >> 3;
                int ce  = g * 64 + (e & 7) * 8;
                cp16(hss + (uint32_t)(row * HS2 + kbase + ce) * 2,
                     hin + (size_t)(b0 + row) * HID + kbase + ce);
            }
            asm volatile("cp.async.commit_group;" ::: "memory");
        }

        float acc[4][4];
        #pragma unroll
        for (int nt = 0; nt < 4; nt++)
            #pragma unroll
            for (int q = 0; q < 4; q++) acc[nt][q] = 0.0f;

#define DO_HALF(K0, PEND)                                                       \
        {                                                                       \
            asm volatile("cp.async.wait_group " #PEND ";" ::: "memory");        \
            __syncwarp();                                                       \
            _Pragma("unroll")                                                   \
            for (int kk = (K0); kk < (K0) + 4; kk++) {                          \
                uint2 v0 = *(const uint2*)&h_s[gid * HS2                        \
                                  + kbase + kk * 16 + 4 * tig];                 \
                uint2 v1 = *(const uint2*)&h_s[(gid + 8) * HS2                  \
                                  + kbase + kk * 16 + 4 * tig];                 \
                uint32_t a[4];                                                  \
                a[0] = v0.x;                                                    \
                a[1] = v1.x;                                                    \
                a[2] = v0.y;                                                    \
                a[3] = v1.y;                                                    \
                _Pragma("unroll")                                               \
                for (int nt = 0; nt < 4; nt++)                                  \
                    mma_f16(acc[nt], a, breg[kk][nt]);                          \
            }                                                                   \
        }
        DO_HALF(0, 1)
        DO_HALF(4, 0)
#undef DO_HALF

        float* rw = red + kw * RED_W;
        #pragma unroll
        for (int nt = 0; nt < 4; nt++) {
            int col = nt * 8 + 2 * tig;
            float* rp = &rw[gid * RED_B + col];
            *(float2*)rp               = make_float2(acc[nt][0], acc[nt][1]);
            *(float2*)(rp + 8 * RED_B) = make_float2(acc[nt][2], acc[nt][3]);
        }
        __syncthreads();                       // bar A

        float s[4];
        #pragma unroll
        for (int g = 0; g < 4; g++) s[g] = xq[g];
        #pragma unroll
        for (int w = 0; w < NKW; w++) {
            const float* rr = red + w * RED_W + rb * RED_B + jl;
            #pragma unroll
            for (int g = 0; g < 4; g++) s[g] += rr[g * 8];
        }
        float iv = sigf(s[0]);
        float fv = sigf(s[1]);
        float gv = tanhf_(s[2]);
        float ov = sigf(s[3]);
        int p = rb * 8 + jl;
        float c = fv * c_s[p] + iv * gv;
        float h = ov * tanhf_(c);
        float z = h0_s[p];                     // h0 == c0
        h = h * mval + z * (1.0f - mval);
        c = c * mval + z * (1.0f - mval);
        c_s[p] = c;
        hout[(size_t)(b0 + rb) * HID + jperm] = __float2half_rn(h);
        __syncwarp();
        if (lane == 0) arrive_release(&g_cnt2[blk * 8]);

        {
            int grow = b0 + rb, gcol = j0 + jl;
            out[(size_t)t * BATCH * HID + grow * HID + gcol] = h;
            if (t == TSTEPS - 1) {
                out[(size_t)TSTEPS * BATCH * HID               + grow * HID + gcol] = h;
                out[(size_t)TSTEPS * BATCH * HID + BATCH * HID + grow * HID + gcol] = c;
            }
        }
        if (t + 1 < TSTEPS) {
            const float* xp = g_xproj + (size_t)(t + 1) * BATCH * GDIM
                            + (size_t)(b0 + rb) * GDIM + j0 + jl;
            #pragma unroll
            for (int g = 0; g < 4; g++) xq[g] = xp[g * HID];
            mval = mask[(t + 1) * BATCH + b0 + rb];
        }
        __syncthreads();                       // bar B
    }
}

// ============================================================================
extern "C" void kernel_launch(void* const* d_in, const int* in_sizes, int n_in,
                              void* d_out, int out_size) {
    const float* inputs = (const float*)d_in[0];   // [512,64,512]
    const float* mask   = (const float*)d_in[1];   // [512,64]
    const float* h0     = (const float*)d_in[2];   // [64,512]
    const float* W_ih   = (const float*)d_in[3];   // [2048,512]
    const float* W_hh   = (const float*)d_in[4];   // [2048,512]
    const float* b_ih   = (const float*)d_in[5];   // [2048]
    const float* b_hh   = (const float*)d_in[6];   // [2048]
    float* out = (float*)d_out;                    // out | hT | cT (fp32)

    const int smem_bytes = BROWS * HS2 * 2 + (NKW * RED_W + 256 + 32) * 4;
    cudaFuncSetAttribute(lstm_kernel, cudaFuncAttributeMaxDynamicSharedMemorySize, smem_bytes);

    dim3 xg(GDIM / 128, (TSTEPS * BATCH) / 128);   // (16, 256)
    xproj_kernel<<<xg, 256>>>(inputs, W_ih, b_ih, b_hh);

    lstm_kernel<<<LSTM_BLOCKS, 128, smem_bytes>>>(mask, h0, W_hh, out);
}